// round 4
// baseline (speedup 1.0000x reference)
#include <cuda_runtime.h>
#include <cuda_bf16.h>
#include <math.h>
#include <stdint.h>

#define B_  4
#define S_  2048
#define D_  1024
#define H_  16
#define HD_ 64
#define M_  (B_ * S_)     // 8192
#define KX_ 3072          // extended K for split-bf16 (3 * 1024)
#define NC_ 48            // K chunks of 64

// ---------------- scratch (static device memory) ---------------------------
__device__ float g_Q[M_ * D_];
__device__ float g_K[M_ * D_];
__device__ float g_V[M_ * D_];
__device__ float g_AO[M_ * D_];
__device__ __nv_bfloat16 g_A2[M_ * KX_];          // split activations
__device__ __nv_bfloat16 g_W2[4 * D_ * KX_];      // split weights (q,k,v,o)
__device__ float g_u[M_];
__device__ float g_lam[B_];
__device__ float g_pmrm[S_];

// ---------------- f32x2 packed helpers --------------------------------------
__device__ __forceinline__ uint64_t pk2(float a, float b) {
    uint64_t r; asm("mov.b64 %0, {%1, %2};" : "=l"(r) : "f"(a), "f"(b)); return r;
}
__device__ __forceinline__ void upk2(uint64_t v, float& a, float& b) {
    asm("mov.b64 {%0, %1}, %2;" : "=f"(a), "=f"(b) : "l"(v));
}
__device__ __forceinline__ uint64_t fma2(uint64_t a, uint64_t b, uint64_t c) {
    uint64_t d; asm("fma.rn.f32x2 %0, %1, %2, %3;" : "=l"(d) : "l"(a), "l"(b), "l"(c)); return d;
}
__device__ __forceinline__ uint64_t mul2(uint64_t a, uint64_t b) {
    uint64_t d; asm("mul.rn.f32x2 %0, %1, %2;" : "=l"(d) : "l"(a), "l"(b)); return d;
}

// ---------------- fast exp on the FMA pipe (no MUFU) ------------------------
// exp(x) for x <= 0. i = rint(x*log2e) clamped to >= -126; 2^f via deg-5 poly.
__device__ __forceinline__ float fexp(float x) {
    float t = x * 1.442695041f;
    t = fmaxf(t, -126.0f);
    int   i = __float2int_rn(t);
    float f = t - (float)i;
    float p = 1.333355815e-3f;
    p = fmaf(p, f, 9.618129107e-3f);
    p = fmaf(p, f, 5.550410866e-2f);
    p = fmaf(p, f, 2.402265069e-1f);
    p = fmaf(p, f, 6.931471806e-1f);
    p = fmaf(p, f, 1.0f);
    return __int_as_float((i + 127) << 23) * p;
}

// ---------------- HMMA helpers ----------------------------------------------
__device__ __forceinline__ uint32_t smem_u32(const void* p) {
    uint32_t a;
    asm("{ .reg .u64 t; cvta.to.shared.u64 t, %1; cvt.u32.u64 %0, t; }" : "=r"(a) : "l"(p));
    return a;
}
__device__ __forceinline__ void ldsm4(uint32_t& r0, uint32_t& r1, uint32_t& r2, uint32_t& r3,
                                      uint32_t addr) {
    asm volatile("ldmatrix.sync.aligned.m8n8.x4.shared.b16 {%0,%1,%2,%3}, [%4];"
                 : "=r"(r0), "=r"(r1), "=r"(r2), "=r"(r3) : "r"(addr));
}
__device__ __forceinline__ void mma_bf16(float* c, const uint32_t* a, uint32_t b0, uint32_t b1) {
    asm volatile("mma.sync.aligned.m16n8k16.row.col.f32.bf16.bf16.f32 "
                 "{%0,%1,%2,%3}, {%4,%5,%6,%7}, {%8,%9}, {%0,%1,%2,%3};"
                 : "+f"(c[0]), "+f"(c[1]), "+f"(c[2]), "+f"(c[3])
                 : "r"(a[0]), "r"(a[1]), "r"(a[2]), "r"(a[3]), "r"(b0), "r"(b1));
}
#define CP_ASYNC16(sm, gm) \
    asm volatile("cp.async.cg.shared.global [%0], [%1], 16;" :: "r"(sm), "l"(gm))
#define CP_COMMIT() asm volatile("cp.async.commit_group;")
#define CP_WAIT1()  asm volatile("cp.async.wait_group 1;")
#define CP_WAIT0()  asm volatile("cp.async.wait_group 0;")

// ---------------- u = ||dx|| / (||x|| + eps) per (b,s) ----------------------
__global__ void __launch_bounds__(256) row_u_kernel(const float* __restrict__ x,
                                                    const float* __restrict__ dx)
{
    const int row = blockIdx.x;
    const float* xr = x  + (size_t)row * D_;
    const float* dr = dx + (size_t)row * D_;
    float sx = 0.f, sd = 0.f;
    for (int c = threadIdx.x; c < D_; c += 256) {
        float a = xr[c]; sx = fmaf(a, a, sx);
        float b = dr[c]; sd = fmaf(b, b, sd);
    }
    __shared__ float shx[32], shd[32];
    int lane = threadIdx.x & 31, wid = threadIdx.x >> 5;
    #pragma unroll
    for (int o = 16; o; o >>= 1) {
        sx += __shfl_xor_sync(0xffffffffu, sx, o);
        sd += __shfl_xor_sync(0xffffffffu, sd, o);
    }
    if (lane == 0) { shx[wid] = sx; shd[wid] = sd; }
    __syncthreads();
    if (wid == 0) {
        sx = (lane < 8) ? shx[lane] : 0.f;
        sd = (lane < 8) ? shd[lane] : 0.f;
        #pragma unroll
        for (int o = 4; o; o >>= 1) {
            sx += __shfl_xor_sync(0xffffffffu, sx, o);
            sd += __shfl_xor_sync(0xffffffffu, sd, o);
        }
        if (lane == 0) g_u[row] = sqrtf(sd) / (sqrtf(sx) + 1e-8f);
    }
}

__global__ void __launch_bounds__(256) lam_kernel()
{
    const int b = blockIdx.x;
    float s = 0.f;
    for (int i = threadIdx.x; i < S_; i += 256) s += g_u[b * S_ + i];
    __shared__ float sh[32];
    int lane = threadIdx.x & 31, wid = threadIdx.x >> 5;
    #pragma unroll
    for (int o = 16; o; o >>= 1) s += __shfl_xor_sync(0xffffffffu, s, o);
    if (lane == 0) sh[wid] = s;
    __syncthreads();
    if (wid == 0) {
        s = (lane < 8) ? sh[lane] : 0.f;
        #pragma unroll
        for (int o = 4; o; o >>= 1) s += __shfl_xor_sync(0xffffffffu, s, o);
        if (lane == 0) g_lam[b] = 10.0f * expf(-5.0f * (s / (float)S_));
    }
}

__global__ void __launch_bounds__(256) pmrm_kernel(const float* __restrict__ pm)
{
    const int q = blockIdx.x;
    float s = 0.f;
    for (int k = threadIdx.x; k < S_; k += 256) s += pm[(size_t)q * S_ + k];
    __shared__ float sh[32];
    int lane = threadIdx.x & 31, wid = threadIdx.x >> 5;
    #pragma unroll
    for (int o = 16; o; o >>= 1) s += __shfl_xor_sync(0xffffffffu, s, o);
    if (lane == 0) sh[wid] = s;
    __syncthreads();
    if (wid == 0) {
        s = (lane < 8) ? sh[lane] : 0.f;
        #pragma unroll
        for (int o = 4; o; o >>= 1) s += __shfl_xor_sync(0xffffffffu, s, o);
        if (lane == 0) g_pmrm[q] = s / (float)S_;
    }
}

// ---------------- split fp32 -> extended-K bf16 -----------------------------
// mode 0 (activations): [hi | lo | hi]; mode 1 (weights): [hi | hi | lo]
template<int MODE>
__global__ void __launch_bounds__(256) split_kernel(const float* __restrict__ src,
                                                    __nv_bfloat16* __restrict__ dst)
{
    const int r = blockIdx.x;
    const int c = threadIdx.x * 4;
    float4 v = *(const float4*)(src + (size_t)r * D_ + c);
    __nv_bfloat16 h0 = __float2bfloat16_rn(v.x);
    __nv_bfloat16 h1 = __float2bfloat16_rn(v.y);
    __nv_bfloat16 h2 = __float2bfloat16_rn(v.z);
    __nv_bfloat16 h3 = __float2bfloat16_rn(v.w);
    __nv_bfloat16 l0 = __float2bfloat16_rn(v.x - __bfloat162float(h0));
    __nv_bfloat16 l1 = __float2bfloat16_rn(v.y - __bfloat162float(h1));
    __nv_bfloat16 l2 = __float2bfloat16_rn(v.z - __bfloat162float(h2));
    __nv_bfloat16 l3 = __float2bfloat16_rn(v.w - __bfloat162float(h3));
    __nv_bfloat162 hA = {h0, h1}, hB = {h2, h3};
    __nv_bfloat162 lA = {l0, l1}, lB = {l2, l3};
    __nv_bfloat16* d0 = dst + (size_t)r * KX_ + c;
    if (MODE == 0) {  // hi, lo, hi
        *(__nv_bfloat162*)(d0)            = hA; *(__nv_bfloat162*)(d0 + 2)        = hB;
        *(__nv_bfloat162*)(d0 + D_)       = lA; *(__nv_bfloat162*)(d0 + D_ + 2)   = lB;
        *(__nv_bfloat162*)(d0 + 2*D_)     = hA; *(__nv_bfloat162*)(d0 + 2*D_ + 2) = hB;
    } else {          // hi, hi, lo
        *(__nv_bfloat162*)(d0)            = hA; *(__nv_bfloat162*)(d0 + 2)        = hB;
        *(__nv_bfloat162*)(d0 + D_)       = hA; *(__nv_bfloat162*)(d0 + D_ + 2)   = hB;
        *(__nv_bfloat162*)(d0 + 2*D_)     = lA; *(__nv_bfloat162*)(d0 + 2*D_ + 2) = lB;
    }
}

// ---------------- HMMA GEMM: C[M,N] = A2 @ W2^T + bias ----------------------
#define GT_TILE 16384   // one 128x64 bf16 tile
#define GT_TOT  (4 * GT_TILE)

__global__ void __launch_bounds__(256) gemm_mma(const __nv_bfloat16* __restrict__ A2,
                                                const __nv_bfloat16* __restrict__ W2base,
                                                const float* __restrict__ b0,
                                                const float* __restrict__ b1,
                                                const float* __restrict__ b2,
                                                float* __restrict__ c0,
                                                float* __restrict__ c1,
                                                float* __restrict__ c2)
{
    extern __shared__ char smem[];
    const uint32_t sA = smem_u32(smem);
    const uint32_t sB = sA + 2 * GT_TILE;

    const int t    = threadIdx.x;
    const int lane = t & 31;
    const int w    = t >> 5;
    const int z    = blockIdx.z;
    const __nv_bfloat16* W2 = W2base + (size_t)z * D_ * KX_;
    const float* bias = (z == 0) ? b0 : (z == 1) ? b1 : b2;
    float* C = (z == 0) ? c0 : (z == 1) ? c1 : c2;

    const int wm = (w & 3) * 32;
    const int wn = (w >> 2) * 64;

    const int ch   = t & 7;
    const int rb   = t >> 3;
    const int swch = ch ^ (rb & 7);
    const __nv_bfloat16* gAp[4];
    const __nv_bfloat16* gBp[4];
    uint32_t smA[4], smB[4];
    #pragma unroll
    for (int p = 0; p < 4; p++) {
        int row = rb + p * 32;
        gAp[p] = A2 + ((size_t)blockIdx.y * 128 + row) * KX_ + ch * 8;
        gBp[p] = W2 + ((size_t)blockIdx.x * 128 + row) * KX_ + ch * 8;
        smA[p] = sA + row * 128 + swch * 16;
        smB[p] = sB + row * 128 + swch * 16;
    }

    float acc[2][8][4];
    #pragma unroll
    for (int i = 0; i < 2; i++)
        #pragma unroll
        for (int j = 0; j < 8; j++)
            #pragma unroll
            for (int k = 0; k < 4; k++) acc[i][j][k] = 0.f;

    #pragma unroll
    for (int p = 0; p < 4; p++) { CP_ASYNC16(smA[p], gAp[p]); CP_ASYNC16(smB[p], gBp[p]); }
    CP_COMMIT();

    const int lrow = lane & 15;
    const int lhalf = lane >> 4;

    for (int kc = 0; kc < NC_; kc++) {
        const int b = kc & 1;
        if (kc + 1 < NC_) {
            const int nb = (kc + 1) & 1;
            const size_t goff = (size_t)(kc + 1) * 64;
            #pragma unroll
            for (int p = 0; p < 4; p++) {
                CP_ASYNC16(smA[p] + nb * GT_TILE, gAp[p] + goff);
                CP_ASYNC16(smB[p] + nb * GT_TILE, gBp[p] + goff);
            }
            CP_COMMIT();
            CP_WAIT1();
        } else {
            CP_WAIT0();
        }
        __syncthreads();

        const uint32_t bA = sA + b * GT_TILE;
        const uint32_t bB = sB + b * GT_TILE;

        #pragma unroll
        for (int ks = 0; ks < 4; ks++) {
            uint32_t af[2][4];
            #pragma unroll
            for (int mi = 0; mi < 2; mi++) {
                int row = wm + mi * 16 + lrow;
                int chk = (ks * 2 + lhalf) ^ (row & 7);
                ldsm4(af[mi][0], af[mi][1], af[mi][2], af[mi][3],
                      bA + row * 128 + chk * 16);
            }
            #pragma unroll
            for (int nj = 0; nj < 4; nj++) {
                uint32_t r0, r1, r2, r3;
                int row = wn + nj * 16 + lrow;
                int chk = (ks * 2 + lhalf) ^ (row & 7);
                ldsm4(r0, r1, r2, r3, bB + row * 128 + chk * 16);
                #pragma unroll
                for (int mi = 0; mi < 2; mi++) {
                    mma_bf16(acc[mi][nj * 2 + 0], af[mi], r0, r2);
                    mma_bf16(acc[mi][nj * 2 + 1], af[mi], r1, r3);
                }
            }
        }
        __syncthreads();
    }

    const int tr = lane >> 2;
    const int tc = (lane & 3) * 2;
    const int gy = blockIdx.y * 128;
    const int gx = blockIdx.x * 128;
    #pragma unroll
    for (int mi = 0; mi < 2; mi++) {
        #pragma unroll
        for (int nj = 0; nj < 8; nj++) {
            int col = gx + wn + nj * 8 + tc;
            float2 bv = *(const float2*)(bias + col);
            int row0 = gy + wm + mi * 16 + tr;
            float2 o0 = { acc[mi][nj][0] + bv.x, acc[mi][nj][1] + bv.y };
            float2 o1 = { acc[mi][nj][2] + bv.x, acc[mi][nj][3] + bv.y };
            *(float2*)(C + (size_t)row0 * D_ + col)       = o0;
            *(float2*)(C + (size_t)(row0 + 8) * D_ + col) = o1;
        }
    }
}

// ---------------- flash attention with bias + clipping (f32x2 + fast exp) ---
__global__ void __launch_bounds__(256) attn_kernel(const float* __restrict__ Q,
                                                   const float* __restrict__ K,
                                                   const float* __restrict__ V,
                                                   const float* __restrict__ pm,
                                                   float* __restrict__ O)
{
    __shared__ float Qs[64][64];
    __shared__ float KP[64][64];
    __shared__ float Vs[64][64];

    const int b = blockIdx.z, h = blockIdx.y, qt = blockIdx.x;
    const int t  = threadIdx.x;
    const int tx = t & 15;
    const int ty = t >> 4;
    const float lamv   = g_lam[b];
    const bool  doclip = (lamv > 1.0f);

    const int lr = t >> 2;
    const int ls = t & 3;

    const size_t qoff = ((size_t)(b * S_) + (size_t)qt * 64) * D_ + h * HD_;
    #pragma unroll
    for (int i = 0; i < 4; i++) {
        int c = (ls + (i << 2)) << 2;
        float4 v = *(const float4*)(Q + qoff + (size_t)lr * D_ + c);
        Qs[lr][c] = v.x; Qs[lr][c + 1] = v.y; Qs[lr][c + 2] = v.z; Qs[lr][c + 3] = v.w;
    }

    float m[4], l[4], thr[4];
    uint64_t acc2[4][2];
    #pragma unroll
    for (int i = 0; i < 4; i++) {
        m[i] = -1e30f; l[i] = 0.f;
        thr[i] = lamv * g_pmrm[qt * 64 + (ty << 2) + i];
        acc2[i][0] = 0ull; acc2[i][1] = 0ull;
    }

    for (int kt = 0; kt < S_ / 64; kt++) {
        __syncthreads();
        const size_t koff = ((size_t)(b * S_) + (size_t)kt * 64) * D_ + h * HD_;
        #pragma unroll
        for (int i = 0; i < 4; i++) {
            int c = (ls + (i << 2)) << 2;
            float4 kv = *(const float4*)(K + koff + (size_t)lr * D_ + c);
            KP[c][lr] = kv.x; KP[c + 1][lr] = kv.y; KP[c + 2][lr] = kv.z; KP[c + 3][lr] = kv.w;
            float4 vv = *(const float4*)(V + koff + (size_t)lr * D_ + c);
            *(float4*)&Vs[lr][c] = vv;
        }
        __syncthreads();

        // scores via packed fp32x2, single LDS.128 per K row-chunk
        uint64_t s2[4][2];
        #pragma unroll
        for (int i = 0; i < 4; i++) { s2[i][0] = 0ull; s2[i][1] = 0ull; }
        #pragma unroll 8
        for (int d = 0; d < 64; d++) {
            ulonglong2 kk = *(const ulonglong2*)&KP[d][tx << 2];
            #pragma unroll
            for (int i = 0; i < 4; i++) {
                float q = Qs[(ty << 2) + i][d];
                uint64_t qq = pk2(q, q);
                s2[i][0] = fma2(qq, kk.x, s2[i][0]);
                s2[i][1] = fma2(qq, kk.y, s2[i][1]);
            }
        }
        float s[4][4];
        #pragma unroll
        for (int i = 0; i < 4; i++) {
            upk2(s2[i][0], s[i][0], s[i][1]);
            upk2(s2[i][1], s[i][2], s[i][3]);
        }

        // bias + clip
        const float* pmr = pm + (size_t)(qt * 64 + (ty << 2)) * S_ + kt * 64 + (tx << 2);
        #pragma unroll
        for (int i = 0; i < 4; i++) {
            #pragma unroll
            for (int j = 0; j < 4; j++) {
                float Lv = fmaf(lamv, pmr[(size_t)i * S_ + j], s[i][j] * 0.125f);
                if (doclip && Lv < thr[i]) Lv = -1e30f;
                s[i][j] = Lv;
            }
        }

        // online softmax (fast exp, FMA pipe)
        #pragma unroll
        for (int i = 0; i < 4; i++) {
            float mloc = fmaxf(fmaxf(s[i][0], s[i][1]), fmaxf(s[i][2], s[i][3]));
            #pragma unroll
            for (int o = 8; o; o >>= 1)
                mloc = fmaxf(mloc, __shfl_xor_sync(0xffffffffu, mloc, o));
            float mnew  = fmaxf(m[i], mloc);
            float scale = fexp(m[i] - mnew);
            float ps = 0.f;
            #pragma unroll
            for (int j = 0; j < 4; j++) {
                s[i][j] = fexp(s[i][j] - mnew);
                ps += s[i][j];
            }
            #pragma unroll
            for (int o = 8; o; o >>= 1)
                ps += __shfl_xor_sync(0xffffffffu, ps, o);
            l[i] = fmaf(l[i], scale, ps);
            m[i] = mnew;
            uint64_t sc2 = pk2(scale, scale);
            acc2[i][0] = mul2(acc2[i][0], sc2);
            acc2[i][1] = mul2(acc2[i][1], sc2);
        }

        __syncthreads();
        #pragma unroll
        for (int i = 0; i < 4; i++)
            #pragma unroll
            for (int j = 0; j < 4; j++)
                KP[(ty << 2) + i][(tx << 2) + j] = s[i][j];
        __syncthreads();

        // AV via packed fp32x2, single LDS.128 per V row-chunk
        #pragma unroll 8
        for (int k = 0; k < 64; k++) {
            ulonglong2 vv = *(const ulonglong2*)&Vs[k][tx << 2];
            #pragma unroll
            for (int i = 0; i < 4; i++) {
                float p = KP[(ty << 2) + i][k];
                uint64_t pp = pk2(p, p);
                acc2[i][0] = fma2(pp, vv.x, acc2[i][0]);
                acc2[i][1] = fma2(pp, vv.y, acc2[i][1]);
            }
        }
    }

    const size_t ooff = ((size_t)(b * S_) + (size_t)qt * 64) * D_ + h * HD_;
    #pragma unroll
    for (int i = 0; i < 4; i++) {
        float inv = 1.0f / l[i];
        float a0, a1, a2, a3;
        upk2(acc2[i][0], a0, a1);
        upk2(acc2[i][1], a2, a3);
        float* orow = O + ooff + (size_t)((ty << 2) + i) * D_ + (tx << 2);
        orow[0] = a0 * inv; orow[1] = a1 * inv; orow[2] = a2 * inv; orow[3] = a3 * inv;
    }
}

// ---------------- launch ----------------------------------------------------
extern "C" void kernel_launch(void* const* d_in, const int* in_sizes, int n_in,
                              void* d_out, int out_size)
{
    const float* x  = (const float*)d_in[0];
    const float* pm = (const float*)d_in[1];
    const float* dx = (const float*)d_in[2];
    const float* wq = (const float*)d_in[3];
    const float* bq = (const float*)d_in[4];
    const float* wk = (const float*)d_in[5];
    const float* bk = (const float*)d_in[6];
    const float* wv = (const float*)d_in[7];
    const float* bv = (const float*)d_in[8];
    const float* wo = (const float*)d_in[9];
    const float* bo = (const float*)d_in[10];
    float* out = (float*)d_out;

    float *gQ, *gK, *gV, *gAO;
    __nv_bfloat16 *gA2, *gW2;
    cudaGetSymbolAddress((void**)&gQ,  g_Q);
    cudaGetSymbolAddress((void**)&gK,  g_K);
    cudaGetSymbolAddress((void**)&gV,  g_V);
    cudaGetSymbolAddress((void**)&gAO, g_AO);
    cudaGetSymbolAddress((void**)&gA2, g_A2);
    cudaGetSymbolAddress((void**)&gW2, g_W2);

    cudaFuncSetAttribute(gemm_mma, cudaFuncAttributeMaxDynamicSharedMemorySize, GT_TOT);

    // scalar stats
    row_u_kernel<<<M_, 256>>>(x, dx);
    lam_kernel<<<B_, 256>>>();
    pmrm_kernel<<<S_, 256>>>(pm);

    // split inputs to extended-K bf16
    split_kernel<0><<<M_, 256>>>(x, gA2);
    split_kernel<1><<<D_, 256>>>(wq, gW2 + 0 * (size_t)D_ * KX_);
    split_kernel<1><<<D_, 256>>>(wk, gW2 + 1 * (size_t)D_ * KX_);
    split_kernel<1><<<D_, 256>>>(wv, gW2 + 2 * (size_t)D_ * KX_);
    split_kernel<1><<<D_, 256>>>(wo, gW2 + 3 * (size_t)D_ * KX_);

    // fused QKV projection (HMMA tensor cores)
    dim3 gqkv(D_ / 128, M_ / 128, 3);
    gemm_mma<<<gqkv, 256, GT_TOT>>>(gA2, gW2, bq, bk, bv, gQ, gK, gV);

    // attention
    dim3 ag(S_ / 64, H_, B_);
    attn_kernel<<<ag, 256>>>(gQ, gK, gV, pm, gAO);

    // output projection
    split_kernel<0><<<M_, 256>>>(gAO, gA2);
    dim3 go(D_ / 128, M_ / 128, 1);
    gemm_mma<<<go, 256, GT_TOT>>>(gA2, gW2 + 3 * (size_t)D_ * KX_, bo, bo, bo, out, out, out);
}

// round 5
// speedup vs baseline: 1.8972x; 1.8972x over previous
#include <cuda_runtime.h>
#include <cuda_bf16.h>
#include <math.h>
#include <stdint.h>

#define B_  4
#define S_  2048
#define D_  1024
#define H_  16
#define HD_ 64
#define M_  (B_ * S_)     // 8192
#define KX_ 3072          // extended K for split-bf16 (3 * 1024)
#define NC_ 48            // GEMM K chunks of 64
#define NIT (S_ / 64)     // attention key tiles = 32

// ---------------- scratch (static device memory) ---------------------------
__device__ __nv_bfloat16 g_A2[M_ * KX_];          // split activations (x, then attn out)
__device__ __nv_bfloat16 g_W2[4 * D_ * KX_];      // split weights (q,k,v,o)
__device__ __nv_bfloat16 g_Qh[M_ * D_], g_Ql[M_ * D_];
__device__ __nv_bfloat16 g_Kh[M_ * D_], g_Kl[M_ * D_];
__device__ __nv_bfloat16 g_Vth[M_ * D_], g_Vtl[M_ * D_];   // V transposed [b][h][d][s]
__device__ float g_u[M_];
__device__ float g_lam[B_];
__device__ float g_pmrm[S_];

// ---------------- helpers ----------------------------------------------------
__device__ __forceinline__ uint32_t smem_u32(const void* p) {
    uint32_t a;
    asm("{ .reg .u64 t; cvta.to.shared.u64 t, %1; cvt.u32.u64 %0, t; }" : "=r"(a) : "l"(p));
    return a;
}
__device__ __forceinline__ void ldsm4(uint32_t& r0, uint32_t& r1, uint32_t& r2, uint32_t& r3,
                                      uint32_t addr) {
    asm volatile("ldmatrix.sync.aligned.m8n8.x4.shared.b16 {%0,%1,%2,%3}, [%4];"
                 : "=r"(r0), "=r"(r1), "=r"(r2), "=r"(r3) : "r"(addr));
}
__device__ __forceinline__ void mma_bf16(float* c, const uint32_t* a, uint32_t b0, uint32_t b1) {
    asm volatile("mma.sync.aligned.m16n8k16.row.col.f32.bf16.bf16.f32 "
                 "{%0,%1,%2,%3}, {%4,%5,%6,%7}, {%8,%9}, {%0,%1,%2,%3};"
                 : "+f"(c[0]), "+f"(c[1]), "+f"(c[2]), "+f"(c[3])
                 : "r"(a[0]), "r"(a[1]), "r"(a[2]), "r"(a[3]), "r"(b0), "r"(b1));
}
#define CP_ASYNC16(sm, gm) \
    asm volatile("cp.async.cg.shared.global [%0], [%1], 16;" :: "r"(sm), "l"(gm))
#define CP_COMMIT() asm volatile("cp.async.commit_group;")
#define CP_WAIT1()  asm volatile("cp.async.wait_group 1;")
#define CP_WAIT0()  asm volatile("cp.async.wait_group 0;")

// pack two floats -> bf16x2 (lo = first arg)
__device__ __forceinline__ uint32_t pk_bf16(float lo, float hi) {
    uint32_t d;
    asm("cvt.rn.bf16x2.f32 %0, %1, %2;" : "=r"(d) : "f"(hi), "f"(lo));
    return d;
}
__device__ __forceinline__ float bf16lo_f(uint32_t v) {
    __nv_bfloat162 b = *(__nv_bfloat162*)&v; return __bfloat162float(b.x);
}
__device__ __forceinline__ float bf16hi_f(uint32_t v) {
    __nv_bfloat162 b = *(__nv_bfloat162*)&v; return __bfloat162float(b.y);
}

// ---------------- stats kernels ----------------------------------------------
__global__ void __launch_bounds__(256) row_u_kernel(const float* __restrict__ x,
                                                    const float* __restrict__ dx)
{
    const int row = blockIdx.x;
    const float* xr = x  + (size_t)row * D_;
    const float* dr = dx + (size_t)row * D_;
    float sx = 0.f, sd = 0.f;
    for (int c = threadIdx.x; c < D_; c += 256) {
        float a = xr[c]; sx = fmaf(a, a, sx);
        float b = dr[c]; sd = fmaf(b, b, sd);
    }
    __shared__ float shx[32], shd[32];
    int lane = threadIdx.x & 31, wid = threadIdx.x >> 5;
    #pragma unroll
    for (int o = 16; o; o >>= 1) {
        sx += __shfl_xor_sync(0xffffffffu, sx, o);
        sd += __shfl_xor_sync(0xffffffffu, sd, o);
    }
    if (lane == 0) { shx[wid] = sx; shd[wid] = sd; }
    __syncthreads();
    if (wid == 0) {
        sx = (lane < 8) ? shx[lane] : 0.f;
        sd = (lane < 8) ? shd[lane] : 0.f;
        #pragma unroll
        for (int o = 4; o; o >>= 1) {
            sx += __shfl_xor_sync(0xffffffffu, sx, o);
            sd += __shfl_xor_sync(0xffffffffu, sd, o);
        }
        if (lane == 0) g_u[row] = sqrtf(sd) / (sqrtf(sx) + 1e-8f);
    }
}

__global__ void __launch_bounds__(256) lam_kernel()
{
    const int b = blockIdx.x;
    float s = 0.f;
    for (int i = threadIdx.x; i < S_; i += 256) s += g_u[b * S_ + i];
    __shared__ float sh[32];
    int lane = threadIdx.x & 31, wid = threadIdx.x >> 5;
    #pragma unroll
    for (int o = 16; o; o >>= 1) s += __shfl_xor_sync(0xffffffffu, s, o);
    if (lane == 0) sh[wid] = s;
    __syncthreads();
    if (wid == 0) {
        s = (lane < 8) ? sh[lane] : 0.f;
        #pragma unroll
        for (int o = 4; o; o >>= 1) s += __shfl_xor_sync(0xffffffffu, s, o);
        if (lane == 0) g_lam[b] = 10.0f * expf(-5.0f * (s / (float)S_));
    }
}

__global__ void __launch_bounds__(256) pmrm_kernel(const float* __restrict__ pm)
{
    const int q = blockIdx.x;
    float s = 0.f;
    for (int k = threadIdx.x; k < S_; k += 256) s += pm[(size_t)q * S_ + k];
    __shared__ float sh[32];
    int lane = threadIdx.x & 31, wid = threadIdx.x >> 5;
    #pragma unroll
    for (int o = 16; o; o >>= 1) s += __shfl_xor_sync(0xffffffffu, s, o);
    if (lane == 0) sh[wid] = s;
    __syncthreads();
    if (wid == 0) {
        s = (lane < 8) ? sh[lane] : 0.f;
        #pragma unroll
        for (int o = 4; o; o >>= 1) s += __shfl_xor_sync(0xffffffffu, s, o);
        if (lane == 0) g_pmrm[q] = s / (float)S_;
    }
}

// ---------------- split fp32 -> extended-K bf16 ------------------------------
// mode 0 (activations): [hi | lo | hi]; mode 1 (weights): [hi | hi | lo]
template<int MODE>
__global__ void __launch_bounds__(256) split_kernel(const float* __restrict__ src,
                                                    __nv_bfloat16* __restrict__ dst)
{
    const int r = blockIdx.x;
    const int c = threadIdx.x * 4;
    float4 v = *(const float4*)(src + (size_t)r * D_ + c);
    __nv_bfloat16 h0 = __float2bfloat16_rn(v.x);
    __nv_bfloat16 h1 = __float2bfloat16_rn(v.y);
    __nv_bfloat16 h2 = __float2bfloat16_rn(v.z);
    __nv_bfloat16 h3 = __float2bfloat16_rn(v.w);
    __nv_bfloat16 l0 = __float2bfloat16_rn(v.x - __bfloat162float(h0));
    __nv_bfloat16 l1 = __float2bfloat16_rn(v.y - __bfloat162float(h1));
    __nv_bfloat16 l2 = __float2bfloat16_rn(v.z - __bfloat162float(h2));
    __nv_bfloat16 l3 = __float2bfloat16_rn(v.w - __bfloat162float(h3));
    __nv_bfloat162 hA = {h0, h1}, hB = {h2, h3};
    __nv_bfloat162 lA = {l0, l1}, lB = {l2, l3};
    __nv_bfloat16* d0 = dst + (size_t)r * KX_ + c;
    if (MODE == 0) {
        *(__nv_bfloat162*)(d0)            = hA; *(__nv_bfloat162*)(d0 + 2)        = hB;
        *(__nv_bfloat162*)(d0 + D_)       = lA; *(__nv_bfloat162*)(d0 + D_ + 2)   = lB;
        *(__nv_bfloat162*)(d0 + 2*D_)     = hA; *(__nv_bfloat162*)(d0 + 2*D_ + 2) = hB;
    } else {
        *(__nv_bfloat162*)(d0)            = hA; *(__nv_bfloat162*)(d0 + 2)        = hB;
        *(__nv_bfloat162*)(d0 + D_)       = hA; *(__nv_bfloat162*)(d0 + D_ + 2)   = hB;
        *(__nv_bfloat162*)(d0 + 2*D_)     = lA; *(__nv_bfloat162*)(d0 + 2*D_ + 2) = lB;
    }
}

// ---------------- HMMA GEMM core (shared by both epilogues) ------------------
#define GT_TILE 16384
#define GT_TOT  (4 * GT_TILE)

// EPI 0: fp32 out (O projection). EPI 1: QKV split-bf16 epilogue.
template<int EPI>
__global__ void __launch_bounds__(256) gemm_mma(const __nv_bfloat16* __restrict__ A2,
                                                const __nv_bfloat16* __restrict__ W2base,
                                                const float* __restrict__ b0,
                                                const float* __restrict__ b1,
                                                const float* __restrict__ b2,
                                                float* __restrict__ cout)
{
    extern __shared__ char smem[];
    const uint32_t sA = smem_u32(smem);
    const uint32_t sB = sA + 2 * GT_TILE;

    const int t    = threadIdx.x;
    const int lane = t & 31;
    const int w    = t >> 5;
    const int z    = blockIdx.z;
    const __nv_bfloat16* W2 = W2base + (size_t)z * D_ * KX_;
    const float* bias = (z == 0) ? b0 : (z == 1) ? b1 : b2;

    const int wm = (w & 3) * 32;
    const int wn = (w >> 2) * 64;

    const int ch   = t & 7;
    const int rb   = t >> 3;
    const int swch = ch ^ (rb & 7);
    const __nv_bfloat16* gAp[4];
    const __nv_bfloat16* gBp[4];
    uint32_t smA[4], smB[4];
    #pragma unroll
    for (int p = 0; p < 4; p++) {
        int row = rb + p * 32;
        gAp[p] = A2 + ((size_t)blockIdx.y * 128 + row) * KX_ + ch * 8;
        gBp[p] = W2 + ((size_t)blockIdx.x * 128 + row) * KX_ + ch * 8;
        smA[p] = sA + row * 128 + swch * 16;
        smB[p] = sB + row * 128 + swch * 16;
    }

    float acc[2][8][4];
    #pragma unroll
    for (int i = 0; i < 2; i++)
        #pragma unroll
        for (int j = 0; j < 8; j++)
            #pragma unroll
            for (int k = 0; k < 4; k++) acc[i][j][k] = 0.f;

    #pragma unroll
    for (int p = 0; p < 4; p++) { CP_ASYNC16(smA[p], gAp[p]); CP_ASYNC16(smB[p], gBp[p]); }
    CP_COMMIT();

    const int lrow = lane & 15;
    const int lhalf = lane >> 4;

    for (int kc = 0; kc < NC_; kc++) {
        const int b = kc & 1;
        if (kc + 1 < NC_) {
            const int nb = (kc + 1) & 1;
            const size_t goff = (size_t)(kc + 1) * 64;
            #pragma unroll
            for (int p = 0; p < 4; p++) {
                CP_ASYNC16(smA[p] + nb * GT_TILE, gAp[p] + goff);
                CP_ASYNC16(smB[p] + nb * GT_TILE, gBp[p] + goff);
            }
            CP_COMMIT();
            CP_WAIT1();
        } else {
            CP_WAIT0();
        }
        __syncthreads();

        const uint32_t bA = sA + b * GT_TILE;
        const uint32_t bB = sB + b * GT_TILE;

        #pragma unroll
        for (int ks = 0; ks < 4; ks++) {
            uint32_t af[2][4];
            #pragma unroll
            for (int mi = 0; mi < 2; mi++) {
                int row = wm + mi * 16 + lrow;
                int chk = (ks * 2 + lhalf) ^ (row & 7);
                ldsm4(af[mi][0], af[mi][1], af[mi][2], af[mi][3],
                      bA + row * 128 + chk * 16);
            }
            #pragma unroll
            for (int nj = 0; nj < 4; nj++) {
                uint32_t r0, r1, r2, r3;
                int row = wn + nj * 16 + lrow;
                int chk = (ks * 2 + lhalf) ^ (row & 7);
                ldsm4(r0, r1, r2, r3, bB + row * 128 + chk * 16);
                #pragma unroll
                for (int mi = 0; mi < 2; mi++) {
                    mma_bf16(acc[mi][nj * 2 + 0], af[mi], r0, r2);
                    mma_bf16(acc[mi][nj * 2 + 1], af[mi], r1, r3);
                }
            }
        }
        __syncthreads();
    }

    const int tr = lane >> 2;
    const int tc = (lane & 3) * 2;
    const int gy = blockIdx.y * 128;
    const int gx = blockIdx.x * 128;

    if (EPI == 0) {
        #pragma unroll
        for (int mi = 0; mi < 2; mi++)
            #pragma unroll
            for (int nj = 0; nj < 8; nj++) {
                int col = gx + wn + nj * 8 + tc;
                float2 bv = *(const float2*)(bias + col);
                int row0 = gy + wm + mi * 16 + tr;
                float2 o0 = { acc[mi][nj][0] + bv.x, acc[mi][nj][1] + bv.y };
                float2 o1 = { acc[mi][nj][2] + bv.x, acc[mi][nj][3] + bv.y };
                *(float2*)(cout + (size_t)row0 * D_ + col)       = o0;
                *(float2*)(cout + (size_t)(row0 + 8) * D_ + col) = o1;
            }
    } else {
        __nv_bfloat16* outh = (z == 0) ? g_Qh : (z == 1) ? g_Kh : g_Vth;
        __nv_bfloat16* outl = (z == 0) ? g_Ql : (z == 1) ? g_Kl : g_Vtl;
        #pragma unroll
        for (int mi = 0; mi < 2; mi++)
            #pragma unroll
            for (int nj = 0; nj < 8; nj++) {
                int col = gx + wn + nj * 8 + tc;
                float2 bv = *(const float2*)(bias + col);
                #pragma unroll
                for (int rr = 0; rr < 2; rr++) {
                    int row = gy + wm + mi * 16 + tr + rr * 8;
                    float v0 = acc[mi][nj][rr * 2 + 0] + bv.x;
                    float v1 = acc[mi][nj][rr * 2 + 1] + bv.y;
                    __nv_bfloat16 h0 = __float2bfloat16_rn(v0);
                    __nv_bfloat16 h1 = __float2bfloat16_rn(v1);
                    __nv_bfloat16 e0 = __float2bfloat16_rn(v0 - __bfloat162float(h0));
                    __nv_bfloat16 e1 = __float2bfloat16_rn(v1 - __bfloat162float(h1));
                    if (z < 2) {
                        __nv_bfloat162 hp = {h0, h1}, lp = {e0, e1};
                        *(__nv_bfloat162*)(outh + (size_t)row * D_ + col) = hp;
                        *(__nv_bfloat162*)(outl + (size_t)row * D_ + col) = lp;
                    } else {
                        // V transposed: [b][h][dl][s]
                        int bb = row >> 11, s = row & 2047;
                        int hh = col >> 6, dl = col & 63;
                        size_t base = ((size_t)(bb * H_ + hh) * 64 + dl) * S_ + s;
                        outh[base] = h0; outl[base] = e0;
                        outh[base + S_] = h1; outl[base + S_] = e1;
                    }
                }
            }
    }
}

// ---------------- HMMA flash attention ---------------------------------------
// 256 threads, 8 warps; each warp owns 16 q-rows (m16). CTA: 128 q x 2048 k.
// smem: Qh/Ql 128x128B, then double-buffered Kh/Kl/Vh/Vl 64x128B tiles.
#define AS_QH 0
#define AS_QL 16384
#define AS_KV 32768      // + buf*32768: [Kh 8K][Kl 8K][Vh 8K][Vl 8K]
#define AS_TOT 98304

__global__ void __launch_bounds__(256) attn_mma(const float* __restrict__ pm,
                                                __nv_bfloat16* __restrict__ A2out)
{
    extern __shared__ char smem[];
    const uint32_t base = smem_u32(smem);
    const int b = blockIdx.z, h = blockIdx.y, qt = blockIdx.x;
    const int t = threadIdx.x;
    const int lane = t & 31;
    const int w = t >> 5;
    const float lamv = g_lam[b];
    const bool doclip = (lamv > 1.0f);

    // ---- Q tile loads (hi+lo), once ----
    #pragma unroll
    for (int i = 0; i < 4; i++) {
        int cid = t + i * 256;             // 0..1023
        int r = cid >> 3, ch = cid & 7;
        size_t go = ((size_t)(b * S_ + qt * 128 + r)) * D_ + h * HD_ + ch * 8;
        uint32_t so = base + AS_QH + r * 128 + ((ch ^ (r & 7)) * 16);
        CP_ASYNC16(so, g_Qh + go);
        CP_ASYNC16(so + AS_QL, g_Ql + go);
    }
    // ---- K/V tile loader ----
    auto load_kv = [&](int kt, int buf) {
        uint32_t sb = base + AS_KV + buf * 32768;
        #pragma unroll
        for (int i = 0; i < 2; i++) {
            int cid = t + i * 256;         // 0..511
            int r = cid >> 3, ch = cid & 7;
            uint32_t sw = (ch ^ (r & 7)) * 16;
            size_t gk = ((size_t)(b * S_ + kt * 64 + r)) * D_ + h * HD_ + ch * 8;
            size_t gv = ((size_t)((b * H_ + h) * 64 + r)) * S_ + kt * 64 + ch * 8;
            uint32_t so = sb + r * 128 + sw;
            CP_ASYNC16(so,         g_Kh + gk);
            CP_ASYNC16(so + 8192,  g_Kl + gk);
            CP_ASYNC16(so + 16384, g_Vth + gv);
            CP_ASYNC16(so + 24576, g_Vtl + gv);
        }
    };
    load_kv(0, 0);
    CP_COMMIT();       // group: Q + KV0
    load_kv(1, 1);
    CP_COMMIT();       // group: KV1

    const int lrow = lane & 15;
    const int lhalf = lane >> 4;
    const int tr = lane >> 2;          // row in fragment
    const int tc = (lane & 3) * 2;     // col pair in fragment
    const int qrow0 = qt * 128 + w * 16 + tr;   // 0..2047 (row for c0,c1)
    const float thr0 = lamv * g_pmrm[qrow0];
    const float thr1 = lamv * g_pmrm[qrow0 + 8];

    float m0 = -1e30f, m1 = -1e30f, l0 = 0.f, l1 = 0.f;
    float oacc[8][4];
    #pragma unroll
    for (int j = 0; j < 8; j++)
        #pragma unroll
        for (int k = 0; k < 4; k++) oacc[j][k] = 0.f;

    const float* pmr0 = pm + (size_t)qrow0 * S_ + tc;
    const float* pmr1 = pmr0 + (size_t)8 * S_;
    const int arow = w * 16 + lrow;

    for (int kt = 0; kt < NIT; kt++) {
        CP_WAIT1();
        __syncthreads();
        const int buf = kt & 1;
        const uint32_t bK = base + AS_KV + buf * 32768;
        const uint32_t bV = bK + 16384;

        // prefetch pm for this tile
        float2 pmv0[8], pmv1[8];
        #pragma unroll
        for (int nt = 0; nt < 8; nt++) {
            pmv0[nt] = *(const float2*)(pmr0 + kt * 64 + nt * 8);
            pmv1[nt] = *(const float2*)(pmr1 + kt * 64 + nt * 8);
        }

        // ---- S = Qh*Kh + Qh*Kl + Ql*Kh ----
        float acc[8][4];
        #pragma unroll
        for (int j = 0; j < 8; j++)
            #pragma unroll
            for (int k = 0; k < 4; k++) acc[j][k] = 0.f;

        #pragma unroll
        for (int ks = 0; ks < 4; ks++) {
            uint32_t ah[4], al[4];
            int achk = ((ks * 2 + lhalf) ^ (arow & 7)) * 16;
            ldsm4(ah[0], ah[1], ah[2], ah[3], base + AS_QH + arow * 128 + achk);
            ldsm4(al[0], al[1], al[2], al[3], base + AS_QL + arow * 128 + achk);
            #pragma unroll
            for (int nj = 0; nj < 4; nj++) {
                int brow = nj * 16 + lrow;
                int bchk = ((ks * 2 + lhalf) ^ (brow & 7)) * 16;
                uint32_t kh0, kh1, kh2, kh3, kl0, kl1, kl2, kl3;
                ldsm4(kh0, kh1, kh2, kh3, bK + brow * 128 + bchk);
                ldsm4(kl0, kl1, kl2, kl3, bK + 8192 + brow * 128 + bchk);
                mma_bf16(acc[nj * 2],     ah, kh0, kh2);
                mma_bf16(acc[nj * 2 + 1], ah, kh1, kh3);
                mma_bf16(acc[nj * 2],     ah, kl0, kl2);
                mma_bf16(acc[nj * 2 + 1], ah, kl1, kl3);
                mma_bf16(acc[nj * 2],     al, kh0, kh2);
                mma_bf16(acc[nj * 2 + 1], al, kh1, kh3);
            }
        }

        // ---- bias + clip + online softmax ----
        float mx0 = -1e30f, mx1 = -1e30f;
        #pragma unroll
        for (int nt = 0; nt < 8; nt++) {
            float L;
            L = fmaf(lamv, pmv0[nt].x, acc[nt][0] * 0.125f);
            if (doclip && L < thr0) L = -1e30f;
            acc[nt][0] = L; mx0 = fmaxf(mx0, L);
            L = fmaf(lamv, pmv0[nt].y, acc[nt][1] * 0.125f);
            if (doclip && L < thr0) L = -1e30f;
            acc[nt][1] = L; mx0 = fmaxf(mx0, L);
            L = fmaf(lamv, pmv1[nt].x, acc[nt][2] * 0.125f);
            if (doclip && L < thr1) L = -1e30f;
            acc[nt][2] = L; mx1 = fmaxf(mx1, L);
            L = fmaf(lamv, pmv1[nt].y, acc[nt][3] * 0.125f);
            if (doclip && L < thr1) L = -1e30f;
            acc[nt][3] = L; mx1 = fmaxf(mx1, L);
        }
        mx0 = fmaxf(mx0, __shfl_xor_sync(0xffffffffu, mx0, 1));
        mx0 = fmaxf(mx0, __shfl_xor_sync(0xffffffffu, mx0, 2));
        mx1 = fmaxf(mx1, __shfl_xor_sync(0xffffffffu, mx1, 1));
        mx1 = fmaxf(mx1, __shfl_xor_sync(0xffffffffu, mx1, 2));
        float mn0 = fmaxf(m0, mx0), mn1 = fmaxf(m1, mx1);
        float sc0 = __expf(m0 - mn0), sc1 = __expf(m1 - mn1);
        float s0 = 0.f, s1 = 0.f;
        #pragma unroll
        for (int nt = 0; nt < 8; nt++) {
            float p;
            p = __expf(acc[nt][0] - mn0); acc[nt][0] = p; s0 += p;
            p = __expf(acc[nt][1] - mn0); acc[nt][1] = p; s0 += p;
            p = __expf(acc[nt][2] - mn1); acc[nt][2] = p; s1 += p;
            p = __expf(acc[nt][3] - mn1); acc[nt][3] = p; s1 += p;
        }
        s0 += __shfl_xor_sync(0xffffffffu, s0, 1);
        s0 += __shfl_xor_sync(0xffffffffu, s0, 2);
        s1 += __shfl_xor_sync(0xffffffffu, s1, 1);
        s1 += __shfl_xor_sync(0xffffffffu, s1, 2);
        l0 = fmaf(l0, sc0, s0); m0 = mn0;
        l1 = fmaf(l1, sc1, s1); m1 = mn1;
        #pragma unroll
        for (int nt = 0; nt < 8; nt++) {
            oacc[nt][0] *= sc0; oacc[nt][1] *= sc0;
            oacc[nt][2] *= sc1; oacc[nt][3] *= sc1;
        }

        // ---- O += Ph*Vh + Ph*Vl + Pl*Vh ----
        #pragma unroll
        for (int ks = 0; ks < 4; ks++) {
            const int na = 2 * ks, nb2 = 2 * ks + 1;
            uint32_t aph[4], apl[4];
            {
                float a0 = acc[na][0],  a1 = acc[na][1];
                float a2 = acc[na][2],  a3 = acc[na][3];
                float b0v = acc[nb2][0], b1v = acc[nb2][1];
                float b2v = acc[nb2][2], b3v = acc[nb2][3];
                aph[0] = pk_bf16(a0, a1);
                aph[1] = pk_bf16(a2, a3);
                aph[2] = pk_bf16(b0v, b1v);
                aph[3] = pk_bf16(b2v, b3v);
                apl[0] = pk_bf16(a0 - bf16lo_f(aph[0]), a1 - bf16hi_f(aph[0]));
                apl[1] = pk_bf16(a2 - bf16lo_f(aph[1]), a3 - bf16hi_f(aph[1]));
                apl[2] = pk_bf16(b0v - bf16lo_f(aph[2]), b1v - bf16hi_f(aph[2]));
                apl[3] = pk_bf16(b2v - bf16lo_f(aph[3]), b3v - bf16hi_f(aph[3]));
            }
            #pragma unroll
            for (int nj = 0; nj < 4; nj++) {
                int brow = nj * 16 + lrow;
                int bchk = ((ks * 2 + lhalf) ^ (brow & 7)) * 16;
                uint32_t vh0, vh1, vh2, vh3, vl0, vl1, vl2, vl3;
                ldsm4(vh0, vh1, vh2, vh3, bV + brow * 128 + bchk);
                ldsm4(vl0, vl1, vl2, vl3, bV + 8192 + brow * 128 + bchk);
                mma_bf16(oacc[nj * 2],     aph, vh0, vh2);
                mma_bf16(oacc[nj * 2 + 1], aph, vh1, vh3);
                mma_bf16(oacc[nj * 2],     aph, vl0, vl2);
                mma_bf16(oacc[nj * 2 + 1], aph, vl1, vl3);
                mma_bf16(oacc[nj * 2],     apl, vh0, vh2);
                mma_bf16(oacc[nj * 2 + 1], apl, vh1, vh3);
            }
        }

        __syncthreads();
        if (kt + 2 < NIT) load_kv(kt + 2, buf);
        CP_COMMIT();
    }

    // ---- epilogue: normalize and write split-bf16 into A2 (hi|lo|hi) ----
    const float inv0 = 1.0f / l0, inv1 = 1.0f / l1;
    const size_t row0 = (size_t)(b * S_) + qt * 128 + w * 16 + tr;
    #pragma unroll
    for (int nt = 0; nt < 8; nt++) {
        int col = h * HD_ + nt * 8 + tc;
        #pragma unroll
        for (int rr = 0; rr < 2; rr++) {
            float v0 = oacc[nt][rr * 2 + 0] * (rr ? inv1 : inv0);
            float v1 = oacc[nt][rr * 2 + 1] * (rr ? inv1 : inv0);
            __nv_bfloat16 h0 = __float2bfloat16_rn(v0);
            __nv_bfloat16 h1 = __float2bfloat16_rn(v1);
            __nv_bfloat16 e0 = __float2bfloat16_rn(v0 - __bfloat162float(h0));
            __nv_bfloat16 e1 = __float2bfloat16_rn(v1 - __bfloat162float(h1));
            __nv_bfloat162 hp = {h0, h1}, lp = {e0, e1};
            __nv_bfloat16* dst = A2out + (row0 + rr * 8) * KX_ + col;
            *(__nv_bfloat162*)(dst)        = hp;
            *(__nv_bfloat162*)(dst + D_)   = lp;
            *(__nv_bfloat162*)(dst + 2*D_) = hp;
        }
    }
}

// ---------------- launch ------------------------------------------------------
extern "C" void kernel_launch(void* const* d_in, const int* in_sizes, int n_in,
                              void* d_out, int out_size)
{
    const float* x  = (const float*)d_in[0];
    const float* pm = (const float*)d_in[1];
    const float* dx = (const float*)d_in[2];
    const float* wq = (const float*)d_in[3];
    const float* bq = (const float*)d_in[4];
    const float* wk = (const float*)d_in[5];
    const float* bk = (const float*)d_in[6];
    const float* wv = (const float*)d_in[7];
    const float* bv = (const float*)d_in[8];
    const float* wo = (const float*)d_in[9];
    const float* bo = (const float*)d_in[10];
    float* out = (float*)d_out;

    __nv_bfloat16 *gA2, *gW2;
    cudaGetSymbolAddress((void**)&gA2, g_A2);
    cudaGetSymbolAddress((void**)&gW2, g_W2);

    cudaFuncSetAttribute(gemm_mma<0>, cudaFuncAttributeMaxDynamicSharedMemorySize, GT_TOT);
    cudaFuncSetAttribute(gemm_mma<1>, cudaFuncAttributeMaxDynamicSharedMemorySize, GT_TOT);
    cudaFuncSetAttribute(attn_mma, cudaFuncAttributeMaxDynamicSharedMemorySize, AS_TOT);

    // scalar stats
    row_u_kernel<<<M_, 256>>>(x, dx);
    lam_kernel<<<B_, 256>>>();
    pmrm_kernel<<<S_, 256>>>(pm);

    // split inputs to extended-K bf16
    split_kernel<0><<<M_, 256>>>(x, gA2);
    split_kernel<1><<<D_, 256>>>(wq, gW2 + 0 * (size_t)D_ * KX_);
    split_kernel<1><<<D_, 256>>>(wk, gW2 + 1 * (size_t)D_ * KX_);
    split_kernel<1><<<D_, 256>>>(wv, gW2 + 2 * (size_t)D_ * KX_);
    split_kernel<1><<<D_, 256>>>(wo, gW2 + 3 * (size_t)D_ * KX_);

    // fused QKV projection -> split-bf16 Q/K/V (V transposed)
    dim3 gqkv(D_ / 128, M_ / 128, 3);
    gemm_mma<1><<<gqkv, 256, GT_TOT>>>(gA2, gW2, bq, bk, bv, nullptr);

    // HMMA flash attention -> writes A2 (hi|lo|hi) directly
    dim3 ag(S_ / 128, H_, B_);
    attn_mma<<<ag, 256, AS_TOT>>>(pm, gA2);

    // output projection
    dim3 go(D_ / 128, M_ / 128, 1);
    gemm_mma<0><<<go, 256, GT_TOT>>>(gA2, gW2 + 3 * (size_t)D_ * KX_, bo, bo, bo, out);
}

// round 6
// speedup vs baseline: 2.0126x; 1.0608x over previous
#include <cuda_runtime.h>
#include <cuda_bf16.h>
#include <math.h>
#include <stdint.h>

#define B_  4
#define S_  2048
#define D_  1024
#define H_  16
#define HD_ 64
#define M_  (B_ * S_)     // 8192
#define KX_ 3072          // extended K for split-bf16 (3 * 1024)
#define NC_ 48            // GEMM K chunks of 64
#define NIT (S_ / 64)     // attention key tiles = 32

// ---------------- scratch (static device memory) ---------------------------
__device__ __nv_bfloat16 g_A2[M_ * KX_];          // split activations (x, then attn out)
__device__ __nv_bfloat16 g_W2[4 * D_ * KX_];      // split weights (q,k,v,o)
__device__ __nv_bfloat16 g_Qh[M_ * D_], g_Ql[M_ * D_];
__device__ __nv_bfloat16 g_Kh[M_ * D_], g_Kl[M_ * D_];
__device__ __nv_bfloat16 g_Vth[M_ * D_], g_Vtl[M_ * D_];   // V transposed [b][h][d][s]
__device__ float g_u[M_];
__device__ float g_lam[B_];
__device__ float g_pmrm[S_];

// ---------------- helpers ----------------------------------------------------
__device__ __forceinline__ uint32_t smem_u32(const void* p) {
    uint32_t a;
    asm("{ .reg .u64 t; cvta.to.shared.u64 t, %1; cvt.u32.u64 %0, t; }" : "=r"(a) : "l"(p));
    return a;
}
__device__ __forceinline__ void ldsm4(uint32_t& r0, uint32_t& r1, uint32_t& r2, uint32_t& r3,
                                      uint32_t addr) {
    asm volatile("ldmatrix.sync.aligned.m8n8.x4.shared.b16 {%0,%1,%2,%3}, [%4];"
                 : "=r"(r0), "=r"(r1), "=r"(r2), "=r"(r3) : "r"(addr));
}
__device__ __forceinline__ void mma_bf16(float* c, const uint32_t* a, uint32_t b0, uint32_t b1) {
    asm volatile("mma.sync.aligned.m16n8k16.row.col.f32.bf16.bf16.f32 "
                 "{%0,%1,%2,%3}, {%4,%5,%6,%7}, {%8,%9}, {%0,%1,%2,%3};"
                 : "+f"(c[0]), "+f"(c[1]), "+f"(c[2]), "+f"(c[3])
                 : "r"(a[0]), "r"(a[1]), "r"(a[2]), "r"(a[3]), "r"(b0), "r"(b1));
}
#define CP_ASYNC16(sm, gm) \
    asm volatile("cp.async.cg.shared.global [%0], [%1], 16;" :: "r"(sm), "l"(gm))
#define CP_COMMIT() asm volatile("cp.async.commit_group;")
#define CP_WAIT1()  asm volatile("cp.async.wait_group 1;")
#define CP_WAIT0()  asm volatile("cp.async.wait_group 0;")

__device__ __forceinline__ uint32_t pk_bf16(float lo, float hi) {
    uint32_t d;
    asm("cvt.rn.bf16x2.f32 %0, %1, %2;" : "=r"(d) : "f"(hi), "f"(lo));
    return d;
}
__device__ __forceinline__ float bf16lo_f(uint32_t v) {
    __nv_bfloat162 b = *(__nv_bfloat162*)&v; return __bfloat162float(b.x);
}
__device__ __forceinline__ float bf16hi_f(uint32_t v) {
    __nv_bfloat162 b = *(__nv_bfloat162*)&v; return __bfloat162float(b.y);
}

// ---------------- merged stats: row_u (8192 blocks) + pmrm (2048 blocks) ----
__global__ void __launch_bounds__(256) stats_kernel(const float* __restrict__ x,
                                                    const float* __restrict__ dx,
                                                    const float* __restrict__ pm)
{
    __shared__ float shx[32], shd[32];
    const int lane = threadIdx.x & 31, wid = threadIdx.x >> 5;
    if (blockIdx.x < M_) {
        const int row = blockIdx.x;
        const float* xr = x  + (size_t)row * D_;
        const float* dr = dx + (size_t)row * D_;
        float sx = 0.f, sd = 0.f;
        for (int c = threadIdx.x; c < D_; c += 256) {
            float a = xr[c]; sx = fmaf(a, a, sx);
            float b = dr[c]; sd = fmaf(b, b, sd);
        }
        #pragma unroll
        for (int o = 16; o; o >>= 1) {
            sx += __shfl_xor_sync(0xffffffffu, sx, o);
            sd += __shfl_xor_sync(0xffffffffu, sd, o);
        }
        if (lane == 0) { shx[wid] = sx; shd[wid] = sd; }
        __syncthreads();
        if (wid == 0) {
            sx = (lane < 8) ? shx[lane] : 0.f;
            sd = (lane < 8) ? shd[lane] : 0.f;
            #pragma unroll
            for (int o = 4; o; o >>= 1) {
                sx += __shfl_xor_sync(0xffffffffu, sx, o);
                sd += __shfl_xor_sync(0xffffffffu, sd, o);
            }
            if (lane == 0) g_u[row] = sqrtf(sd) / (sqrtf(sx) + 1e-8f);
        }
    } else {
        const int q = blockIdx.x - M_;
        float s = 0.f;
        for (int k = threadIdx.x; k < S_; k += 256) s += pm[(size_t)q * S_ + k];
        #pragma unroll
        for (int o = 16; o; o >>= 1) s += __shfl_xor_sync(0xffffffffu, s, o);
        if (lane == 0) shx[wid] = s;
        __syncthreads();
        if (wid == 0) {
            s = (lane < 8) ? shx[lane] : 0.f;
            #pragma unroll
            for (int o = 4; o; o >>= 1) s += __shfl_xor_sync(0xffffffffu, s, o);
            if (lane == 0) g_pmrm[q] = s / (float)S_;
        }
    }
}

__global__ void __launch_bounds__(256) lam_kernel()
{
    const int b = blockIdx.x;
    float s = 0.f;
    for (int i = threadIdx.x; i < S_; i += 256) s += g_u[b * S_ + i];
    __shared__ float sh[32];
    int lane = threadIdx.x & 31, wid = threadIdx.x >> 5;
    #pragma unroll
    for (int o = 16; o; o >>= 1) s += __shfl_xor_sync(0xffffffffu, s, o);
    if (lane == 0) sh[wid] = s;
    __syncthreads();
    if (wid == 0) {
        s = (lane < 8) ? sh[lane] : 0.f;
        #pragma unroll
        for (int o = 4; o; o >>= 1) s += __shfl_xor_sync(0xffffffffu, s, o);
        if (lane == 0) g_lam[b] = 10.0f * expf(-5.0f * (s / (float)S_));
    }
}

// ---------------- merged split: x (mode0) + 4 weights (mode1) ----------------
__global__ void __launch_bounds__(256) split_all(const float* __restrict__ x,
                                                 const float* __restrict__ wq,
                                                 const float* __restrict__ wk,
                                                 const float* __restrict__ wv,
                                                 const float* __restrict__ wo)
{
    const int rg = blockIdx.x;
    const float* src;
    __nv_bfloat16* dst;
    int mode;
    if (rg < M_) {
        src = x + (size_t)rg * D_;
        dst = g_A2 + (size_t)rg * KX_;
        mode = 0;
    } else {
        int idx = rg - M_;
        int j = idx >> 10;
        int row = idx & 1023;
        const float* w = (j == 0) ? wq : (j == 1) ? wk : (j == 2) ? wv : wo;
        src = w + (size_t)row * D_;
        dst = g_W2 + ((size_t)j * D_ + row) * KX_;
        mode = 1;
    }
    const int c = threadIdx.x * 4;
    float4 v = *(const float4*)(src + c);
    __nv_bfloat16 h0 = __float2bfloat16_rn(v.x);
    __nv_bfloat16 h1 = __float2bfloat16_rn(v.y);
    __nv_bfloat16 h2 = __float2bfloat16_rn(v.z);
    __nv_bfloat16 h3 = __float2bfloat16_rn(v.w);
    __nv_bfloat16 l0 = __float2bfloat16_rn(v.x - __bfloat162float(h0));
    __nv_bfloat16 l1 = __float2bfloat16_rn(v.y - __bfloat162float(h1));
    __nv_bfloat16 l2 = __float2bfloat16_rn(v.z - __bfloat162float(h2));
    __nv_bfloat16 l3 = __float2bfloat16_rn(v.w - __bfloat162float(h3));
    __nv_bfloat162 hA = {h0, h1}, hB = {h2, h3};
    __nv_bfloat162 lA = {l0, l1}, lB = {l2, l3};
    __nv_bfloat16* d0 = dst + c;
    if (mode == 0) {  // hi | lo | hi
        *(__nv_bfloat162*)(d0)            = hA; *(__nv_bfloat162*)(d0 + 2)        = hB;
        *(__nv_bfloat162*)(d0 + D_)       = lA; *(__nv_bfloat162*)(d0 + D_ + 2)   = lB;
        *(__nv_bfloat162*)(d0 + 2*D_)     = hA; *(__nv_bfloat162*)(d0 + 2*D_ + 2) = hB;
    } else {          // hi | hi | lo
        *(__nv_bfloat162*)(d0)            = hA; *(__nv_bfloat162*)(d0 + 2)        = hB;
        *(__nv_bfloat162*)(d0 + D_)       = hA; *(__nv_bfloat162*)(d0 + D_ + 2)   = hB;
        *(__nv_bfloat162*)(d0 + 2*D_)     = lA; *(__nv_bfloat162*)(d0 + 2*D_ + 2) = lB;
    }
}

// ---------------- HMMA GEMM (3-stage cp.async pipeline) -----------------------
// 128x128 CTA tile, BK=64; grid.x covers stacked N (EPI1: q|k|v = 24 blocks).
#define GST 16384
#define GT_TOT (6 * GST)      // 3 stages x (A + B)

template<int EPI>
__global__ void __launch_bounds__(256) gemm_mma(const __nv_bfloat16* __restrict__ A2,
                                                const __nv_bfloat16* __restrict__ W2,
                                                const float* __restrict__ b0,
                                                const float* __restrict__ b1,
                                                const float* __restrict__ b2,
                                                float* __restrict__ cout)
{
    extern __shared__ char smem[];
    const uint32_t sA = smem_u32(smem);
    const uint32_t sB = sA + 3 * GST;

    const int t    = threadIdx.x;
    const int lane = t & 31;
    const int w    = t >> 5;
    const int z    = blockIdx.x >> 3;          // which matrix (bias/output select)
    const float* bias = (z == 0) ? b0 : (z == 1) ? b1 : b2;

    const int wm = (w & 3) * 32;
    const int wn = (w >> 2) * 64;

    const int ch   = t & 7;
    const int rb   = t >> 3;
    const int swch = ch ^ (rb & 7);
    const __nv_bfloat16* gAp[4];
    const __nv_bfloat16* gBp[4];
    uint32_t smA[4], smB[4];
    #pragma unroll
    for (int p = 0; p < 4; p++) {
        int row = rb + p * 32;
        gAp[p] = A2 + ((size_t)blockIdx.y * 128 + row) * KX_ + ch * 8;
        gBp[p] = W2 + ((size_t)blockIdx.x * 128 + row) * KX_ + ch * 8;
        smA[p] = sA + row * 128 + swch * 16;
        smB[p] = sB + row * 128 + swch * 16;
    }

    auto load_chunk = [&](int kc, int st) {
        const size_t goff = (size_t)kc * 64;
        #pragma unroll
        for (int p = 0; p < 4; p++) {
            CP_ASYNC16(smA[p] + st * GST, gAp[p] + goff);
            CP_ASYNC16(smB[p] + st * GST, gBp[p] + goff);
        }
    };

    float acc[2][8][4];
    #pragma unroll
    for (int i = 0; i < 2; i++)
        #pragma unroll
        for (int j = 0; j < 8; j++)
            #pragma unroll
            for (int k = 0; k < 4; k++) acc[i][j][k] = 0.f;

    load_chunk(0, 0); CP_COMMIT();
    load_chunk(1, 1); CP_COMMIT();

    const int lrow = lane & 15;
    const int lhalf = lane >> 4;

    int st = 0;
    for (int kc = 0; kc < NC_; kc++) {
        CP_WAIT1();
        __syncthreads();
        if (kc + 2 < NC_) {
            int ns = st + 2; if (ns >= 3) ns -= 3;
            load_chunk(kc + 2, ns);
        }
        CP_COMMIT();

        const uint32_t bA = sA + st * GST;
        const uint32_t bB = sB + st * GST;

        #pragma unroll
        for (int ks = 0; ks < 4; ks++) {
            uint32_t af[2][4];
            #pragma unroll
            for (int mi = 0; mi < 2; mi++) {
                int row = wm + mi * 16 + lrow;
                int chk = (ks * 2 + lhalf) ^ (row & 7);
                ldsm4(af[mi][0], af[mi][1], af[mi][2], af[mi][3],
                      bA + row * 128 + chk * 16);
            }
            #pragma unroll
            for (int nj = 0; nj < 4; nj++) {
                uint32_t r0, r1, r2, r3;
                int row = wn + nj * 16 + lrow;
                int chk = (ks * 2 + lhalf) ^ (row & 7);
                ldsm4(r0, r1, r2, r3, bB + row * 128 + chk * 16);
                #pragma unroll
                for (int mi = 0; mi < 2; mi++) {
                    mma_bf16(acc[mi][nj * 2 + 0], af[mi], r0, r2);
                    mma_bf16(acc[mi][nj * 2 + 1], af[mi], r1, r3);
                }
            }
        }
        if (++st == 3) st = 0;
    }

    const int tr = lane >> 2;
    const int tc = (lane & 3) * 2;
    const int gy = blockIdx.y * 128;
    const int gxz = (blockIdx.x & 7) * 128;     // column within the z-th matrix

    if (EPI == 0) {
        #pragma unroll
        for (int mi = 0; mi < 2; mi++)
            #pragma unroll
            for (int nj = 0; nj < 8; nj++) {
                int col = gxz + wn + nj * 8 + tc;
                float2 bv = *(const float2*)(bias + col);
                int row0 = gy + wm + mi * 16 + tr;
                float2 o0 = { acc[mi][nj][0] + bv.x, acc[mi][nj][1] + bv.y };
                float2 o1 = { acc[mi][nj][2] + bv.x, acc[mi][nj][3] + bv.y };
                *(float2*)(cout + (size_t)row0 * D_ + col)       = o0;
                *(float2*)(cout + (size_t)(row0 + 8) * D_ + col) = o1;
            }
    } else {
        __nv_bfloat16* outh = (z == 0) ? g_Qh : (z == 1) ? g_Kh : g_Vth;
        __nv_bfloat16* outl = (z == 0) ? g_Ql : (z == 1) ? g_Kl : g_Vtl;
        #pragma unroll
        for (int mi = 0; mi < 2; mi++)
            #pragma unroll
            for (int nj = 0; nj < 8; nj++) {
                int col = gxz + wn + nj * 8 + tc;
                float2 bv = *(const float2*)(bias + col);
                #pragma unroll
                for (int rr = 0; rr < 2; rr++) {
                    int row = gy + wm + mi * 16 + tr + rr * 8;
                    float v0 = acc[mi][nj][rr * 2 + 0] + bv.x;
                    float v1 = acc[mi][nj][rr * 2 + 1] + bv.y;
                    __nv_bfloat16 h0 = __float2bfloat16_rn(v0);
                    __nv_bfloat16 h1 = __float2bfloat16_rn(v1);
                    __nv_bfloat16 e0 = __float2bfloat16_rn(v0 - __bfloat162float(h0));
                    __nv_bfloat16 e1 = __float2bfloat16_rn(v1 - __bfloat162float(h1));
                    if (z < 2) {
                        __nv_bfloat162 hp = {h0, h1}, lp = {e0, e1};
                        *(__nv_bfloat162*)(outh + (size_t)row * D_ + col) = hp;
                        *(__nv_bfloat162*)(outl + (size_t)row * D_ + col) = lp;
                    } else {
                        int bb = row >> 11, s = row & 2047;
                        int hh = col >> 6, dl = col & 63;
                        size_t base = ((size_t)(bb * H_ + hh) * 64 + dl) * S_ + s;
                        outh[base] = h0; outl[base] = e0;
                        outh[base + S_] = h1; outl[base + S_] = e1;
                    }
                }
            }
    }
}

// ---------------- HMMA flash attention ---------------------------------------
#define AS_QH 0
#define AS_QL 16384
#define AS_KV 32768
#define AS_TOT 98304

__global__ void __launch_bounds__(256, 2) attn_mma(const float* __restrict__ pm,
                                                   __nv_bfloat16* __restrict__ A2out)
{
    extern __shared__ char smem[];
    const uint32_t base = smem_u32(smem);
    const int b = blockIdx.z, h = blockIdx.y, qt = blockIdx.x;
    const int t = threadIdx.x;
    const int lane = t & 31;
    const int w = t >> 5;
    const float lamv = g_lam[b];
    const bool doclip = (lamv > 1.0f);

    #pragma unroll
    for (int i = 0; i < 4; i++) {
        int cid = t + i * 256;
        int r = cid >> 3, ch = cid & 7;
        size_t go = ((size_t)(b * S_ + qt * 128 + r)) * D_ + h * HD_ + ch * 8;
        uint32_t so = base + AS_QH + r * 128 + ((ch ^ (r & 7)) * 16);
        CP_ASYNC16(so, g_Qh + go);
        CP_ASYNC16(so + AS_QL, g_Ql + go);
    }
    auto load_kv = [&](int kt, int buf) {
        uint32_t sb = base + AS_KV + buf * 32768;
        #pragma unroll
        for (int i = 0; i < 2; i++) {
            int cid = t + i * 256;
            int r = cid >> 3, ch = cid & 7;
            uint32_t sw = (ch ^ (r & 7)) * 16;
            size_t gk = ((size_t)(b * S_ + kt * 64 + r)) * D_ + h * HD_ + ch * 8;
            size_t gv = ((size_t)((b * H_ + h) * 64 + r)) * S_ + kt * 64 + ch * 8;
            uint32_t so = sb + r * 128 + sw;
            CP_ASYNC16(so,         g_Kh + gk);
            CP_ASYNC16(so + 8192,  g_Kl + gk);
            CP_ASYNC16(so + 16384, g_Vth + gv);
            CP_ASYNC16(so + 24576, g_Vtl + gv);
        }
    };
    load_kv(0, 0);
    CP_COMMIT();
    load_kv(1, 1);
    CP_COMMIT();

    const int lrow = lane & 15;
    const int lhalf = lane >> 4;
    const int tr = lane >> 2;
    const int tc = (lane & 3) * 2;
    const int qrow0 = qt * 128 + w * 16 + tr;
    const float thr0 = lamv * g_pmrm[qrow0];
    const float thr1 = lamv * g_pmrm[qrow0 + 8];

    float m0 = -1e30f, m1 = -1e30f, l0 = 0.f, l1 = 0.f;
    float oacc[8][4];
    #pragma unroll
    for (int j = 0; j < 8; j++)
        #pragma unroll
        for (int k = 0; k < 4; k++) oacc[j][k] = 0.f;

    const float* pmr0 = pm + (size_t)qrow0 * S_ + tc;
    const float* pmr1 = pmr0 + (size_t)8 * S_;
    const int arow = w * 16 + lrow;

    for (int kt = 0; kt < NIT; kt++) {
        CP_WAIT1();
        __syncthreads();
        const int buf = kt & 1;
        const uint32_t bK = base + AS_KV + buf * 32768;
        const uint32_t bV = bK + 16384;

        float acc[8][4];
        #pragma unroll
        for (int j = 0; j < 8; j++)
            #pragma unroll
            for (int k = 0; k < 4; k++) acc[j][k] = 0.f;

        #pragma unroll
        for (int ks = 0; ks < 4; ks++) {
            uint32_t ah[4], al[4];
            int achk = ((ks * 2 + lhalf) ^ (arow & 7)) * 16;
            ldsm4(ah[0], ah[1], ah[2], ah[3], base + AS_QH + arow * 128 + achk);
            ldsm4(al[0], al[1], al[2], al[3], base + AS_QL + arow * 128 + achk);
            #pragma unroll
            for (int nj = 0; nj < 4; nj++) {
                int brow = nj * 16 + lrow;
                int bchk = ((ks * 2 + lhalf) ^ (brow & 7)) * 16;
                uint32_t kh0, kh1, kh2, kh3, kl0, kl1, kl2, kl3;
                ldsm4(kh0, kh1, kh2, kh3, bK + brow * 128 + bchk);
                ldsm4(kl0, kl1, kl2, kl3, bK + 8192 + brow * 128 + bchk);
                mma_bf16(acc[nj * 2],     ah, kh0, kh2);
                mma_bf16(acc[nj * 2 + 1], ah, kh1, kh3);
                mma_bf16(acc[nj * 2],     ah, kl0, kl2);
                mma_bf16(acc[nj * 2 + 1], ah, kl1, kl3);
                mma_bf16(acc[nj * 2],     al, kh0, kh2);
                mma_bf16(acc[nj * 2 + 1], al, kh1, kh3);
            }
        }

        // bias + clip + online softmax (pm loaded inline; L2-resident)
        float mx0 = -1e30f, mx1 = -1e30f;
        #pragma unroll
        for (int nt = 0; nt < 8; nt++) {
            float2 p0 = *(const float2*)(pmr0 + kt * 64 + nt * 8);
            float2 p1 = *(const float2*)(pmr1 + kt * 64 + nt * 8);
            float L;
            L = fmaf(lamv, p0.x, acc[nt][0] * 0.125f);
            if (doclip && L < thr0) L = -1e30f;
            acc[nt][0] = L; mx0 = fmaxf(mx0, L);
            L = fmaf(lamv, p0.y, acc[nt][1] * 0.125f);
            if (doclip && L < thr0) L = -1e30f;
            acc[nt][1] = L; mx0 = fmaxf(mx0, L);
            L = fmaf(lamv, p1.x, acc[nt][2] * 0.125f);
            if (doclip && L < thr1) L = -1e30f;
            acc[nt][2] = L; mx1 = fmaxf(mx1, L);
            L = fmaf(lamv, p1.y, acc[nt][3] * 0.125f);
            if (doclip && L < thr1) L = -1e30f;
            acc[nt][3] = L; mx1 = fmaxf(mx1, L);
        }
        mx0 = fmaxf(mx0, __shfl_xor_sync(0xffffffffu, mx0, 1));
        mx0 = fmaxf(mx0, __shfl_xor_sync(0xffffffffu, mx0, 2));
        mx1 = fmaxf(mx1, __shfl_xor_sync(0xffffffffu, mx1, 1));
        mx1 = fmaxf(mx1, __shfl_xor_sync(0xffffffffu, mx1, 2));
        float mn0 = fmaxf(m0, mx0), mn1 = fmaxf(m1, mx1);
        float sc0 = __expf(m0 - mn0), sc1 = __expf(m1 - mn1);
        float s0 = 0.f, s1 = 0.f;
        #pragma unroll
        for (int nt = 0; nt < 8; nt++) {
            float p;
            p = __expf(acc[nt][0] - mn0); acc[nt][0] = p; s0 += p;
            p = __expf(acc[nt][1] - mn0); acc[nt][1] = p; s0 += p;
            p = __expf(acc[nt][2] - mn1); acc[nt][2] = p; s1 += p;
            p = __expf(acc[nt][3] - mn1); acc[nt][3] = p; s1 += p;
        }
        s0 += __shfl_xor_sync(0xffffffffu, s0, 1);
        s0 += __shfl_xor_sync(0xffffffffu, s0, 2);
        s1 += __shfl_xor_sync(0xffffffffu, s1, 1);
        s1 += __shfl_xor_sync(0xffffffffu, s1, 2);
        l0 = fmaf(l0, sc0, s0); m0 = mn0;
        l1 = fmaf(l1, sc1, s1); m1 = mn1;
        #pragma unroll
        for (int nt = 0; nt < 8; nt++) {
            oacc[nt][0] *= sc0; oacc[nt][1] *= sc0;
            oacc[nt][2] *= sc1; oacc[nt][3] *= sc1;
        }

        #pragma unroll
        for (int ks = 0; ks < 4; ks++) {
            const int na = 2 * ks, nb2 = 2 * ks + 1;
            uint32_t aph[4], apl[4];
            {
                float a0 = acc[na][0],  a1 = acc[na][1];
                float a2 = acc[na][2],  a3 = acc[na][3];
                float b0v = acc[nb2][0], b1v = acc[nb2][1];
                float b2v = acc[nb2][2], b3v = acc[nb2][3];
                aph[0] = pk_bf16(a0, a1);
                aph[1] = pk_bf16(a2, a3);
                aph[2] = pk_bf16(b0v, b1v);
                aph[3] = pk_bf16(b2v, b3v);
                apl[0] = pk_bf16(a0 - bf16lo_f(aph[0]), a1 - bf16hi_f(aph[0]));
                apl[1] = pk_bf16(a2 - bf16lo_f(aph[1]), a3 - bf16hi_f(aph[1]));
                apl[2] = pk_bf16(b0v - bf16lo_f(aph[2]), b1v - bf16hi_f(aph[2]));
                apl[3] = pk_bf16(b2v - bf16lo_f(aph[3]), b3v - bf16hi_f(aph[3]));
            }
            #pragma unroll
            for (int nj = 0; nj < 4; nj++) {
                int brow = nj * 16 + lrow;
                int bchk = ((ks * 2 + lhalf) ^ (brow & 7)) * 16;
                uint32_t vh0, vh1, vh2, vh3, vl0, vl1, vl2, vl3;
                ldsm4(vh0, vh1, vh2, vh3, bV + brow * 128 + bchk);
                ldsm4(vl0, vl1, vl2, vl3, bV + 8192 + brow * 128 + bchk);
                mma_bf16(oacc[nj * 2],     aph, vh0, vh2);
                mma_bf16(oacc[nj * 2 + 1], aph, vh1, vh3);
                mma_bf16(oacc[nj * 2],     aph, vl0, vl2);
                mma_bf16(oacc[nj * 2 + 1], aph, vl1, vl3);
                mma_bf16(oacc[nj * 2],     apl, vh0, vh2);
                mma_bf16(oacc[nj * 2 + 1], apl, vh1, vh3);
            }
        }

        __syncthreads();
        if (kt + 2 < NIT) load_kv(kt + 2, buf);
        CP_COMMIT();
    }

    const float inv0 = 1.0f / l0, inv1 = 1.0f / l1;
    const size_t row0 = (size_t)(b * S_) + qt * 128 + w * 16 + tr;
    #pragma unroll
    for (int nt = 0; nt < 8; nt++) {
        int col = h * HD_ + nt * 8 + tc;
        #pragma unroll
        for (int rr = 0; rr < 2; rr++) {
            float v0 = oacc[nt][rr * 2 + 0] * (rr ? inv1 : inv0);
            float v1 = oacc[nt][rr * 2 + 1] * (rr ? inv1 : inv0);
            __nv_bfloat16 h0 = __float2bfloat16_rn(v0);
            __nv_bfloat16 h1 = __float2bfloat16_rn(v1);
            __nv_bfloat16 e0 = __float2bfloat16_rn(v0 - __bfloat162float(h0));
            __nv_bfloat16 e1 = __float2bfloat16_rn(v1 - __bfloat162float(h1));
            __nv_bfloat162 hp = {h0, h1}, lp = {e0, e1};
            __nv_bfloat16* dst = A2out + (row0 + rr * 8) * KX_ + col;
            *(__nv_bfloat162*)(dst)        = hp;
            *(__nv_bfloat162*)(dst + D_)   = lp;
            *(__nv_bfloat162*)(dst + 2*D_) = hp;
        }
    }
}

// ---------------- launch ------------------------------------------------------
extern "C" void kernel_launch(void* const* d_in, const int* in_sizes, int n_in,
                              void* d_out, int out_size)
{
    const float* x  = (const float*)d_in[0];
    const float* pm = (const float*)d_in[1];
    const float* dx = (const float*)d_in[2];
    const float* wq = (const float*)d_in[3];
    const float* bq = (const float*)d_in[4];
    const float* wk = (const float*)d_in[5];
    const float* bk = (const float*)d_in[6];
    const float* wv = (const float*)d_in[7];
    const float* bv = (const float*)d_in[8];
    const float* wo = (const float*)d_in[9];
    const float* bo = (const float*)d_in[10];
    float* out = (float*)d_out;

    __nv_bfloat16 *gA2, *gW2;
    cudaGetSymbolAddress((void**)&gA2, g_A2);
    cudaGetSymbolAddress((void**)&gW2, g_W2);

    cudaFuncSetAttribute(gemm_mma<0>, cudaFuncAttributeMaxDynamicSharedMemorySize, GT_TOT);
    cudaFuncSetAttribute(gemm_mma<1>, cudaFuncAttributeMaxDynamicSharedMemorySize, GT_TOT);
    cudaFuncSetAttribute(attn_mma, cudaFuncAttributeMaxDynamicSharedMemorySize, AS_TOT);

    // stats (merged) + lam
    stats_kernel<<<M_ + S_, 256>>>(x, dx, pm);
    lam_kernel<<<B_, 256>>>();

    // merged splits (x + 4 weights)
    split_all<<<M_ + 4 * D_, 256>>>(x, wq, wk, wv, wo);

    // fused QKV projection: single GEMM, N = 3072 (q|k|v stacked)
    dim3 gqkv(3 * D_ / 128, M_ / 128);
    gemm_mma<1><<<gqkv, 256, GT_TOT>>>(gA2, gW2, bq, bk, bv, nullptr);

    // HMMA flash attention -> writes A2 (hi|lo|hi) directly
    dim3 ag(S_ / 128, H_, B_);
    attn_mma<<<ag, 256, AS_TOT>>>(pm, gA2);

    // output projection
    dim3 go(D_ / 128, M_ / 128);
    gemm_mma<0><<<go, 256, GT_TOT>>>(gA2, gW2 + 3 * (size_t)D_ * KX_, bo, bo, bo, out);
}

// round 7
// speedup vs baseline: 2.2686x; 1.1272x over previous
#include <cuda_runtime.h>
#include <cuda_bf16.h>
#include <cuda_fp16.h>
#include <math.h>
#include <stdint.h>

#define B_  4
#define S_  2048
#define D_  1024
#define H_  16
#define HD_ 64
#define M_  (B_ * S_)     // 8192
#define KX_ 3072          // extended K for split-bf16 (3 * 1024)
#define NC_ 48            // GEMM K chunks of 64
#define NIT (S_ / 64)     // attention key tiles = 32

// ---------------- scratch (static device memory) ---------------------------
__device__ __nv_bfloat16 g_A2[M_ * KX_];          // split activations (x, then attn out)
__device__ __nv_bfloat16 g_W2[4 * D_ * KX_];      // split weights (q,k,v,o)
__device__ __half g_Qh[M_ * D_], g_Ql[M_ * D_];
__device__ __half g_Kh[M_ * D_], g_Kl[M_ * D_];
__device__ __half g_Vth[M_ * D_], g_Vtl[M_ * D_];   // V transposed [b][h][d][s]
__device__ float g_u[M_];
__device__ float g_lam[B_];
__device__ float g_pmrm[S_];

// ---------------- helpers ----------------------------------------------------
__device__ __forceinline__ uint32_t smem_u32(const void* p) {
    uint32_t a;
    asm("{ .reg .u64 t; cvta.to.shared.u64 t, %1; cvt.u32.u64 %0, t; }" : "=r"(a) : "l"(p));
    return a;
}
__device__ __forceinline__ void ldsm4(uint32_t& r0, uint32_t& r1, uint32_t& r2, uint32_t& r3,
                                      uint32_t addr) {
    asm volatile("ldmatrix.sync.aligned.m8n8.x4.shared.b16 {%0,%1,%2,%3}, [%4];"
                 : "=r"(r0), "=r"(r1), "=r"(r2), "=r"(r3) : "r"(addr));
}
__device__ __forceinline__ void mma_bf16(float* c, const uint32_t* a, uint32_t b0, uint32_t b1) {
    asm volatile("mma.sync.aligned.m16n8k16.row.col.f32.bf16.bf16.f32 "
                 "{%0,%1,%2,%3}, {%4,%5,%6,%7}, {%8,%9}, {%0,%1,%2,%3};"
                 : "+f"(c[0]), "+f"(c[1]), "+f"(c[2]), "+f"(c[3])
                 : "r"(a[0]), "r"(a[1]), "r"(a[2]), "r"(a[3]), "r"(b0), "r"(b1));
}
__device__ __forceinline__ void mma_f16(float* c, const uint32_t* a, uint32_t b0, uint32_t b1) {
    asm volatile("mma.sync.aligned.m16n8k16.row.col.f32.f16.f16.f32 "
                 "{%0,%1,%2,%3}, {%4,%5,%6,%7}, {%8,%9}, {%0,%1,%2,%3};"
                 : "+f"(c[0]), "+f"(c[1]), "+f"(c[2]), "+f"(c[3])
                 : "r"(a[0]), "r"(a[1]), "r"(a[2]), "r"(a[3]), "r"(b0), "r"(b1));
}
#define CP_ASYNC16(sm, gm) \
    asm volatile("cp.async.cg.shared.global [%0], [%1], 16;" :: "r"(sm), "l"(gm))
#define CP_COMMIT() asm volatile("cp.async.commit_group;")
#define CP_WAIT1()  asm volatile("cp.async.wait_group 1;")
#define CP_WAIT0()  asm volatile("cp.async.wait_group 0;")

// pack two floats -> f16x2 (first arg = low half)
__device__ __forceinline__ uint32_t pk_f16(float lo, float hi) {
    uint32_t d;
    asm("cvt.rn.f16x2.f32 %0, %1, %2;" : "=r"(d) : "f"(hi), "f"(lo));
    return d;
}

// ---------------- fused prologue: split x + weights, row_u, pmrm -------------
// blocks [0, M_): x rows (split mode0 + row_u)
// blocks [M_, M_+4096): weight rows (split mode1)
// blocks [M_+4096, M_+4096+S_): pmrm rows
__global__ void __launch_bounds__(256) prologue(const float* __restrict__ x,
                                                const float* __restrict__ dx,
                                                const float* __restrict__ pm,
                                                const float* __restrict__ wq,
                                                const float* __restrict__ wk,
                                                const float* __restrict__ wv,
                                                const float* __restrict__ wo)
{
    __shared__ float shx[32], shd[32];
    const int rg = blockIdx.x;
    const int lane = threadIdx.x & 31, wid = threadIdx.x >> 5;

    if (rg >= M_ + 4 * D_) {                 // ---- pmrm ----
        const int q = rg - M_ - 4 * D_;
        float s = 0.f;
        for (int k = threadIdx.x; k < S_; k += 256) s += pm[(size_t)q * S_ + k];
        #pragma unroll
        for (int o = 16; o; o >>= 1) s += __shfl_xor_sync(0xffffffffu, s, o);
        if (lane == 0) shx[wid] = s;
        __syncthreads();
        if (wid == 0) {
            s = (lane < 8) ? shx[lane] : 0.f;
            #pragma unroll
            for (int o = 4; o; o >>= 1) s += __shfl_xor_sync(0xffffffffu, s, o);
            if (lane == 0) g_pmrm[q] = s / (float)S_;
        }
        return;
    }

    const int c = threadIdx.x * 4;
    const float* src;
    __nv_bfloat16* dst;
    int mode;
    if (rg < M_) {
        src = x + (size_t)rg * D_;
        dst = g_A2 + (size_t)rg * KX_;
        mode = 0;
    } else {
        int idx = rg - M_;
        int j = idx >> 10;
        int row = idx & 1023;
        const float* w = (j == 0) ? wq : (j == 1) ? wk : (j == 2) ? wv : wo;
        src = w + (size_t)row * D_;
        dst = g_W2 + ((size_t)j * D_ + row) * KX_;
        mode = 1;
    }
    float4 v = *(const float4*)(src + c);
    __nv_bfloat16 h0 = __float2bfloat16_rn(v.x);
    __nv_bfloat16 h1 = __float2bfloat16_rn(v.y);
    __nv_bfloat16 h2 = __float2bfloat16_rn(v.z);
    __nv_bfloat16 h3 = __float2bfloat16_rn(v.w);
    __nv_bfloat16 l0 = __float2bfloat16_rn(v.x - __bfloat162float(h0));
    __nv_bfloat16 l1 = __float2bfloat16_rn(v.y - __bfloat162float(h1));
    __nv_bfloat16 l2 = __float2bfloat16_rn(v.z - __bfloat162float(h2));
    __nv_bfloat16 l3 = __float2bfloat16_rn(v.w - __bfloat162float(h3));
    __nv_bfloat162 hA = {h0, h1}, hB = {h2, h3};
    __nv_bfloat162 lA = {l0, l1}, lB = {l2, l3};
    __nv_bfloat16* d0 = dst + c;
    if (mode == 0) {  // hi | lo | hi
        *(__nv_bfloat162*)(d0)            = hA; *(__nv_bfloat162*)(d0 + 2)        = hB;
        *(__nv_bfloat162*)(d0 + D_)       = lA; *(__nv_bfloat162*)(d0 + D_ + 2)   = lB;
        *(__nv_bfloat162*)(d0 + 2*D_)     = hA; *(__nv_bfloat162*)(d0 + 2*D_ + 2) = hB;
        // row_u for this x row
        float4 dv = *(const float4*)(dx + (size_t)rg * D_ + c);
        float sx = v.x*v.x + v.y*v.y + v.z*v.z + v.w*v.w;
        float sd = dv.x*dv.x + dv.y*dv.y + dv.z*dv.z + dv.w*dv.w;
        #pragma unroll
        for (int o = 16; o; o >>= 1) {
            sx += __shfl_xor_sync(0xffffffffu, sx, o);
            sd += __shfl_xor_sync(0xffffffffu, sd, o);
        }
        if (lane == 0) { shx[wid] = sx; shd[wid] = sd; }
        __syncthreads();
        if (wid == 0) {
            sx = (lane < 8) ? shx[lane] : 0.f;
            sd = (lane < 8) ? shd[lane] : 0.f;
            #pragma unroll
            for (int o = 4; o; o >>= 1) {
                sx += __shfl_xor_sync(0xffffffffu, sx, o);
                sd += __shfl_xor_sync(0xffffffffu, sd, o);
            }
            if (lane == 0) g_u[rg] = sqrtf(sd) / (sqrtf(sx) + 1e-8f);
        }
    } else {          // hi | hi | lo
        *(__nv_bfloat162*)(d0)            = hA; *(__nv_bfloat162*)(d0 + 2)        = hB;
        *(__nv_bfloat162*)(d0 + D_)       = hA; *(__nv_bfloat162*)(d0 + D_ + 2)   = hB;
        *(__nv_bfloat162*)(d0 + 2*D_)     = lA; *(__nv_bfloat162*)(d0 + 2*D_ + 2) = lB;
    }
}

__global__ void __launch_bounds__(256) lam_kernel()
{
    const int b = blockIdx.x;
    float s = 0.f;
    for (int i = threadIdx.x; i < S_; i += 256) s += g_u[b * S_ + i];
    __shared__ float sh[32];
    int lane = threadIdx.x & 31, wid = threadIdx.x >> 5;
    #pragma unroll
    for (int o = 16; o; o >>= 1) s += __shfl_xor_sync(0xffffffffu, s, o);
    if (lane == 0) sh[wid] = s;
    __syncthreads();
    if (wid == 0) {
        s = (lane < 8) ? sh[lane] : 0.f;
        #pragma unroll
        for (int o = 4; o; o >>= 1) s += __shfl_xor_sync(0xffffffffu, s, o);
        if (lane == 0) g_lam[b] = 10.0f * expf(-5.0f * (s / (float)S_));
    }
}

// ---------------- HMMA GEMM (3-stage cp.async pipeline) -----------------------
#define GST 16384
#define GT_TOT (6 * GST)

template<int EPI>
__global__ void __launch_bounds__(256, 2) gemm_mma(const __nv_bfloat16* __restrict__ A2,
                                                   const __nv_bfloat16* __restrict__ W2,
                                                   const float* __restrict__ b0,
                                                   const float* __restrict__ b1,
                                                   const float* __restrict__ b2,
                                                   float* __restrict__ cout)
{
    extern __shared__ char smem[];
    const uint32_t sA = smem_u32(smem);
    const uint32_t sB = sA + 3 * GST;

    const int t    = threadIdx.x;
    const int lane = t & 31;
    const int w    = t >> 5;
    const int z    = blockIdx.x >> 3;
    const float* bias = (z == 0) ? b0 : (z == 1) ? b1 : b2;

    const int wm = (w & 3) * 32;
    const int wn = (w >> 2) * 64;

    const int ch   = t & 7;
    const int rb   = t >> 3;
    const int swch = ch ^ (rb & 7);
    const __nv_bfloat16* gAp[4];
    const __nv_bfloat16* gBp[4];
    uint32_t smA[4], smB[4];
    #pragma unroll
    for (int p = 0; p < 4; p++) {
        int row = rb + p * 32;
        gAp[p] = A2 + ((size_t)blockIdx.y * 128 + row) * KX_ + ch * 8;
        gBp[p] = W2 + ((size_t)blockIdx.x * 128 + row) * KX_ + ch * 8;
        smA[p] = sA + row * 128 + swch * 16;
        smB[p] = sB + row * 128 + swch * 16;
    }

    auto load_chunk = [&](int kc, int st) {
        const size_t goff = (size_t)kc * 64;
        #pragma unroll
        for (int p = 0; p < 4; p++) {
            CP_ASYNC16(smA[p] + st * GST, gAp[p] + goff);
            CP_ASYNC16(smB[p] + st * GST, gBp[p] + goff);
        }
    };

    float acc[2][8][4];
    #pragma unroll
    for (int i = 0; i < 2; i++)
        #pragma unroll
        for (int j = 0; j < 8; j++)
            #pragma unroll
            for (int k = 0; k < 4; k++) acc[i][j][k] = 0.f;

    load_chunk(0, 0); CP_COMMIT();
    load_chunk(1, 1); CP_COMMIT();

    const int lrow = lane & 15;
    const int lhalf = lane >> 4;

    int st = 0;
    for (int kc = 0; kc < NC_; kc++) {
        CP_WAIT1();
        __syncthreads();
        if (kc + 2 < NC_) {
            int ns = st + 2; if (ns >= 3) ns -= 3;
            load_chunk(kc + 2, ns);
        }
        CP_COMMIT();

        const uint32_t bA = sA + st * GST;
        const uint32_t bB = sB + st * GST;

        #pragma unroll
        for (int ks = 0; ks < 4; ks++) {
            uint32_t af[2][4];
            #pragma unroll
            for (int mi = 0; mi < 2; mi++) {
                int row = wm + mi * 16 + lrow;
                int chk = (ks * 2 + lhalf) ^ (row & 7);
                ldsm4(af[mi][0], af[mi][1], af[mi][2], af[mi][3],
                      bA + row * 128 + chk * 16);
            }
            #pragma unroll
            for (int nj = 0; nj < 4; nj++) {
                uint32_t r0, r1, r2, r3;
                int row = wn + nj * 16 + lrow;
                int chk = (ks * 2 + lhalf) ^ (row & 7);
                ldsm4(r0, r1, r2, r3, bB + row * 128 + chk * 16);
                #pragma unroll
                for (int mi = 0; mi < 2; mi++) {
                    mma_bf16(acc[mi][nj * 2 + 0], af[mi], r0, r2);
                    mma_bf16(acc[mi][nj * 2 + 1], af[mi], r1, r3);
                }
            }
        }
        if (++st == 3) st = 0;
    }

    const int tr = lane >> 2;
    const int tc = (lane & 3) * 2;
    const int gy = blockIdx.y * 128;
    const int gxz = (blockIdx.x & 7) * 128;

    if (EPI == 0) {
        #pragma unroll
        for (int mi = 0; mi < 2; mi++)
            #pragma unroll
            for (int nj = 0; nj < 8; nj++) {
                int col = gxz + wn + nj * 8 + tc;
                float2 bv = *(const float2*)(bias + col);
                int row0 = gy + wm + mi * 16 + tr;
                float2 o0 = { acc[mi][nj][0] + bv.x, acc[mi][nj][1] + bv.y };
                float2 o1 = { acc[mi][nj][2] + bv.x, acc[mi][nj][3] + bv.y };
                *(float2*)(cout + (size_t)row0 * D_ + col)       = o0;
                *(float2*)(cout + (size_t)(row0 + 8) * D_ + col) = o1;
            }
    } else {
        __half* outh = (z == 0) ? g_Qh : (z == 1) ? g_Kh : g_Vth;
        __half* outl = (z == 0) ? g_Ql : (z == 1) ? g_Kl : g_Vtl;
        #pragma unroll
        for (int mi = 0; mi < 2; mi++)
            #pragma unroll
            for (int nj = 0; nj < 8; nj++) {
                int col = gxz + wn + nj * 8 + tc;
                float2 bv = *(const float2*)(bias + col);
                #pragma unroll
                for (int rr = 0; rr < 2; rr++) {
                    int row = gy + wm + mi * 16 + tr + rr * 8;
                    float v0 = acc[mi][nj][rr * 2 + 0] + bv.x;
                    float v1 = acc[mi][nj][rr * 2 + 1] + bv.y;
                    __half h0 = __float2half_rn(v0);
                    __half h1 = __float2half_rn(v1);
                    __half e0 = __float2half_rn(v0 - __half2float(h0));
                    __half e1 = __float2half_rn(v1 - __half2float(h1));
                    if (z < 2) {
                        __half2 hp = {h0, h1}, lp = {e0, e1};
                        *(__half2*)(outh + (size_t)row * D_ + col) = hp;
                        *(__half2*)(outl + (size_t)row * D_ + col) = lp;
                    } else {
                        int bb = row >> 11, s = row & 2047;
                        int hh = col >> 6, dl = col & 63;
                        size_t base = ((size_t)(bb * H_ + hh) * 64 + dl) * S_ + s;
                        outh[base] = h0; outl[base] = e0;
                        outh[base + S_] = h1; outl[base + S_] = e1;
                    }
                }
            }
    }
}

// ---------------- HMMA flash attention (fp16; PV 2-product) -------------------
#define AS_QH 0
#define AS_QL 16384
#define AS_KV 32768
#define AS_TOT 98304

__global__ void __launch_bounds__(256, 2) attn_mma(const float* __restrict__ pm,
                                                   __nv_bfloat16* __restrict__ A2out)
{
    extern __shared__ char smem[];
    const uint32_t base = smem_u32(smem);
    const int b = blockIdx.z, h = blockIdx.y, qt = blockIdx.x;
    const int t = threadIdx.x;
    const int lane = t & 31;
    const int w = t >> 5;
    const float lamv = g_lam[b];
    const bool doclip = (lamv > 1.0f);

    #pragma unroll
    for (int i = 0; i < 4; i++) {
        int cid = t + i * 256;
        int r = cid >> 3, ch = cid & 7;
        size_t go = ((size_t)(b * S_ + qt * 128 + r)) * D_ + h * HD_ + ch * 8;
        uint32_t so = base + AS_QH + r * 128 + ((ch ^ (r & 7)) * 16);
        CP_ASYNC16(so, g_Qh + go);
        CP_ASYNC16(so + AS_QL, g_Ql + go);
    }
    auto load_kv = [&](int kt, int buf) {
        uint32_t sb = base + AS_KV + buf * 32768;
        #pragma unroll
        for (int i = 0; i < 2; i++) {
            int cid = t + i * 256;
            int r = cid >> 3, ch = cid & 7;
            uint32_t sw = (ch ^ (r & 7)) * 16;
            size_t gk = ((size_t)(b * S_ + kt * 64 + r)) * D_ + h * HD_ + ch * 8;
            size_t gv = ((size_t)((b * H_ + h) * 64 + r)) * S_ + kt * 64 + ch * 8;
            uint32_t so = sb + r * 128 + sw;
            CP_ASYNC16(so,         g_Kh + gk);
            CP_ASYNC16(so + 8192,  g_Kl + gk);
            CP_ASYNC16(so + 16384, g_Vth + gv);
            CP_ASYNC16(so + 24576, g_Vtl + gv);
        }
    };
    load_kv(0, 0);
    CP_COMMIT();
    load_kv(1, 1);
    CP_COMMIT();

    const int lrow = lane & 15;
    const int lhalf = lane >> 4;
    const int tr = lane >> 2;
    const int tc = (lane & 3) * 2;
    const int qrow0 = qt * 128 + w * 16 + tr;
    const float thr0 = lamv * g_pmrm[qrow0];
    const float thr1 = lamv * g_pmrm[qrow0 + 8];

    float m0 = -1e30f, m1 = -1e30f, l0 = 0.f, l1 = 0.f;
    float oacc[8][4];
    #pragma unroll
    for (int j = 0; j < 8; j++)
        #pragma unroll
        for (int k = 0; k < 4; k++) oacc[j][k] = 0.f;

    const float* pmr0 = pm + (size_t)qrow0 * S_ + tc;
    const float* pmr1 = pmr0 + (size_t)8 * S_;
    const int arow = w * 16 + lrow;

    for (int kt = 0; kt < NIT; kt++) {
        CP_WAIT1();
        __syncthreads();
        const int buf = kt & 1;
        const uint32_t bK = base + AS_KV + buf * 32768;
        const uint32_t bV = bK + 16384;

        // prefetch pm for this tile (hides LDG under QK mma)
        float2 pmv0[8], pmv1[8];
        #pragma unroll
        for (int nt = 0; nt < 8; nt++) {
            pmv0[nt] = *(const float2*)(pmr0 + kt * 64 + nt * 8);
            pmv1[nt] = *(const float2*)(pmr1 + kt * 64 + nt * 8);
        }

        float acc[8][4];
        #pragma unroll
        for (int j = 0; j < 8; j++)
            #pragma unroll
            for (int k = 0; k < 4; k++) acc[j][k] = 0.f;

        // ---- S = Qh*Kh + Qh*Kl + Ql*Kh (fp16 limbs) ----
        #pragma unroll
        for (int ks = 0; ks < 4; ks++) {
            uint32_t ah[4], al[4];
            int achk = ((ks * 2 + lhalf) ^ (arow & 7)) * 16;
            ldsm4(ah[0], ah[1], ah[2], ah[3], base + AS_QH + arow * 128 + achk);
            ldsm4(al[0], al[1], al[2], al[3], base + AS_QL + arow * 128 + achk);
            #pragma unroll
            for (int nj = 0; nj < 4; nj++) {
                int brow = nj * 16 + lrow;
                int bchk = ((ks * 2 + lhalf) ^ (brow & 7)) * 16;
                uint32_t kh0, kh1, kh2, kh3, kl0, kl1, kl2, kl3;
                ldsm4(kh0, kh1, kh2, kh3, bK + brow * 128 + bchk);
                ldsm4(kl0, kl1, kl2, kl3, bK + 8192 + brow * 128 + bchk);
                mma_f16(acc[nj * 2],     ah, kh0, kh2);
                mma_f16(acc[nj * 2 + 1], ah, kh1, kh3);
                mma_f16(acc[nj * 2],     ah, kl0, kl2);
                mma_f16(acc[nj * 2 + 1], ah, kl1, kl3);
                mma_f16(acc[nj * 2],     al, kh0, kh2);
                mma_f16(acc[nj * 2 + 1], al, kh1, kh3);
            }
        }

        // ---- bias + clip + online softmax ----
        float mx0 = -1e30f, mx1 = -1e30f;
        #pragma unroll
        for (int nt = 0; nt < 8; nt++) {
            float L;
            L = fmaf(lamv, pmv0[nt].x, acc[nt][0] * 0.125f);
            if (doclip && L < thr0) L = -1e30f;
            acc[nt][0] = L; mx0 = fmaxf(mx0, L);
            L = fmaf(lamv, pmv0[nt].y, acc[nt][1] * 0.125f);
            if (doclip && L < thr0) L = -1e30f;
            acc[nt][1] = L; mx0 = fmaxf(mx0, L);
            L = fmaf(lamv, pmv1[nt].x, acc[nt][2] * 0.125f);
            if (doclip && L < thr1) L = -1e30f;
            acc[nt][2] = L; mx1 = fmaxf(mx1, L);
            L = fmaf(lamv, pmv1[nt].y, acc[nt][3] * 0.125f);
            if (doclip && L < thr1) L = -1e30f;
            acc[nt][3] = L; mx1 = fmaxf(mx1, L);
        }
        mx0 = fmaxf(mx0, __shfl_xor_sync(0xffffffffu, mx0, 1));
        mx0 = fmaxf(mx0, __shfl_xor_sync(0xffffffffu, mx0, 2));
        mx1 = fmaxf(mx1, __shfl_xor_sync(0xffffffffu, mx1, 1));
        mx1 = fmaxf(mx1, __shfl_xor_sync(0xffffffffu, mx1, 2));
        float mn0 = fmaxf(m0, mx0), mn1 = fmaxf(m1, mx1);
        float sc0 = __expf(m0 - mn0), sc1 = __expf(m1 - mn1);
        float s0 = 0.f, s1 = 0.f;
        #pragma unroll
        for (int nt = 0; nt < 8; nt++) {
            float p;
            p = __expf(acc[nt][0] - mn0); acc[nt][0] = p; s0 += p;
            p = __expf(acc[nt][1] - mn0); acc[nt][1] = p; s0 += p;
            p = __expf(acc[nt][2] - mn1); acc[nt][2] = p; s1 += p;
            p = __expf(acc[nt][3] - mn1); acc[nt][3] = p; s1 += p;
        }
        s0 += __shfl_xor_sync(0xffffffffu, s0, 1);
        s0 += __shfl_xor_sync(0xffffffffu, s0, 2);
        s1 += __shfl_xor_sync(0xffffffffu, s1, 1);
        s1 += __shfl_xor_sync(0xffffffffu, s1, 2);
        l0 = fmaf(l0, sc0, s0); m0 = mn0;
        l1 = fmaf(l1, sc1, s1); m1 = mn1;
        #pragma unroll
        for (int nt = 0; nt < 8; nt++) {
            oacc[nt][0] *= sc0; oacc[nt][1] *= sc0;
            oacc[nt][2] *= sc1; oacc[nt][3] *= sc1;
        }

        // ---- O += Ph*Vh + Ph*Vl (P single-limb fp16, V 2-limb fp16) ----
        #pragma unroll
        for (int ks = 0; ks < 4; ks++) {
            const int na = 2 * ks, nb2 = 2 * ks + 1;
            uint32_t aph[4];
            aph[0] = pk_f16(acc[na][0],  acc[na][1]);
            aph[1] = pk_f16(acc[na][2],  acc[na][3]);
            aph[2] = pk_f16(acc[nb2][0], acc[nb2][1]);
            aph[3] = pk_f16(acc[nb2][2], acc[nb2][3]);
            #pragma unroll
            for (int nj = 0; nj < 4; nj++) {
                int brow = nj * 16 + lrow;
                int bchk = ((ks * 2 + lhalf) ^ (brow & 7)) * 16;
                uint32_t vh0, vh1, vh2, vh3, vl0, vl1, vl2, vl3;
                ldsm4(vh0, vh1, vh2, vh3, bV + brow * 128 + bchk);
                ldsm4(vl0, vl1, vl2, vl3, bV + 8192 + brow * 128 + bchk);
                mma_f16(oacc[nj * 2],     aph, vh0, vh2);
                mma_f16(oacc[nj * 2 + 1], aph, vh1, vh3);
                mma_f16(oacc[nj * 2],     aph, vl0, vl2);
                mma_f16(oacc[nj * 2 + 1], aph, vl1, vl3);
            }
        }

        __syncthreads();
        if (kt + 2 < NIT) load_kv(kt + 2, buf);
        CP_COMMIT();
    }

    const float inv0 = 1.0f / l0, inv1 = 1.0f / l1;
    const size_t row0 = (size_t)(b * S_) + qt * 128 + w * 16 + tr;
    #pragma unroll
    for (int nt = 0; nt < 8; nt++) {
        int col = h * HD_ + nt * 8 + tc;
        #pragma unroll
        for (int rr = 0; rr < 2; rr++) {
            float v0 = oacc[nt][rr * 2 + 0] * (rr ? inv1 : inv0);
            float v1 = oacc[nt][rr * 2 + 1] * (rr ? inv1 : inv0);
            __nv_bfloat16 h0 = __float2bfloat16_rn(v0);
            __nv_bfloat16 h1 = __float2bfloat16_rn(v1);
            __nv_bfloat16 e0 = __float2bfloat16_rn(v0 - __bfloat162float(h0));
            __nv_bfloat16 e1 = __float2bfloat16_rn(v1 - __bfloat162float(h1));
            __nv_bfloat162 hp = {h0, h1}, lp = {e0, e1};
            __nv_bfloat16* dst = A2out + (row0 + rr * 8) * KX_ + col;
            *(__nv_bfloat162*)(dst)        = hp;
            *(__nv_bfloat162*)(dst + D_)   = lp;
            *(__nv_bfloat162*)(dst + 2*D_) = hp;
        }
    }
}

// ---------------- launch ------------------------------------------------------
extern "C" void kernel_launch(void* const* d_in, const int* in_sizes, int n_in,
                              void* d_out, int out_size)
{
    const float* x  = (const float*)d_in[0];
    const float* pm = (const float*)d_in[1];
    const float* dx = (const float*)d_in[2];
    const float* wq = (const float*)d_in[3];
    const float* bq = (const float*)d_in[4];
    const float* wk = (const float*)d_in[5];
    const float* bk = (const float*)d_in[6];
    const float* wv = (const float*)d_in[7];
    const float* bv = (const float*)d_in[8];
    const float* wo = (const float*)d_in[9];
    const float* bo = (const float*)d_in[10];
    float* out = (float*)d_out;

    __nv_bfloat16 *gA2, *gW2;
    cudaGetSymbolAddress((void**)&gA2, g_A2);
    cudaGetSymbolAddress((void**)&gW2, g_W2);

    cudaFuncSetAttribute(gemm_mma<0>, cudaFuncAttributeMaxDynamicSharedMemorySize, GT_TOT);
    cudaFuncSetAttribute(gemm_mma<1>, cudaFuncAttributeMaxDynamicSharedMemorySize, GT_TOT);
    cudaFuncSetAttribute(attn_mma, cudaFuncAttributeMaxDynamicSharedMemorySize, AS_TOT);

    // fused prologue: splits + row_u + pmrm, then lam
    prologue<<<M_ + 4 * D_ + S_, 256>>>(x, dx, pm, wq, wk, wv, wo);
    lam_kernel<<<B_, 256>>>();

    // fused QKV projection: single GEMM, N = 3072 (q|k|v stacked)
    dim3 gqkv(3 * D_ / 128, M_ / 128);
    gemm_mma<1><<<gqkv, 256, GT_TOT>>>(gA2, gW2, bq, bk, bv, nullptr);

    // HMMA flash attention (fp16) -> writes A2 (hi|lo|hi) directly
    dim3 ag(S_ / 128, H_, B_);
    attn_mma<<<ag, 256, AS_TOT>>>(pm, gA2);

    // output projection
    dim3 go(D_ / 128, M_ / 128);
    gemm_mma<0><<<go, 256, GT_TOT>>>(gA2, gW2 + 3 * (size_t)D_ * KX_, bo, bo, bo, out);
}

// round 8
// speedup vs baseline: 2.8687x; 1.2645x over previous
#include <cuda_runtime.h>
#include <cuda_bf16.h>
#include <cuda_fp16.h>
#include <math.h>
#include <stdint.h>

#define B_  4
#define S_  2048
#define D_  1024
#define H_  16
#define HD_ 64
#define M_  (B_ * S_)     // 8192
#define KX_ 2048          // extended K for 2-term fp16 split
#define NC_ 32            // GEMM K chunks of 64
#define NIT (S_ / 64)     // attention key tiles = 32

// ---------------- scratch (static device memory) ---------------------------
__device__ __half g_A2[M_ * KX_];          // split activations: [xh | xl]
__device__ __half g_W2[4 * D_ * KX_];      // weights: [Wh | Wh] (q,k,v,o)
__device__ __half g_Qh[M_ * D_];
__device__ __half g_Kh[M_ * D_], g_Kl[M_ * D_];
__device__ __half g_Vth[M_ * D_], g_Vtl[M_ * D_];   // V transposed [b][h][d][s]
__device__ float g_u[M_];
__device__ float g_lam[B_];
__device__ float g_pmrm[S_];

// ---------------- helpers ----------------------------------------------------
__device__ __forceinline__ uint32_t smem_u32(const void* p) {
    uint32_t a;
    asm("{ .reg .u64 t; cvta.to.shared.u64 t, %1; cvt.u32.u64 %0, t; }" : "=r"(a) : "l"(p));
    return a;
}
__device__ __forceinline__ void ldsm4(uint32_t& r0, uint32_t& r1, uint32_t& r2, uint32_t& r3,
                                      uint32_t addr) {
    asm volatile("ldmatrix.sync.aligned.m8n8.x4.shared.b16 {%0,%1,%2,%3}, [%4];"
                 : "=r"(r0), "=r"(r1), "=r"(r2), "=r"(r3) : "r"(addr));
}
__device__ __forceinline__ void mma_f16(float* c, const uint32_t* a, uint32_t b0, uint32_t b1) {
    asm volatile("mma.sync.aligned.m16n8k16.row.col.f32.f16.f16.f32 "
                 "{%0,%1,%2,%3}, {%4,%5,%6,%7}, {%8,%9}, {%0,%1,%2,%3};"
                 : "+f"(c[0]), "+f"(c[1]), "+f"(c[2]), "+f"(c[3])
                 : "r"(a[0]), "r"(a[1]), "r"(a[2]), "r"(a[3]), "r"(b0), "r"(b1));
}
#define CP_ASYNC16(sm, gm) \
    asm volatile("cp.async.cg.shared.global [%0], [%1], 16;" :: "r"(sm), "l"(gm))
#define CP_COMMIT() asm volatile("cp.async.commit_group;")
#define CP_WAIT1()  asm volatile("cp.async.wait_group 1;")
#define CP_WAIT0()  asm volatile("cp.async.wait_group 0;")

__device__ __forceinline__ uint32_t pk_f16(float lo, float hi) {
    uint32_t d;
    asm("cvt.rn.f16x2.f32 %0, %1, %2;" : "=r"(d) : "f"(hi), "f"(lo));
    return d;
}

// ---------------- fused prologue: split x + weights, row_u, pmrm -------------
__global__ void __launch_bounds__(256) prologue(const float* __restrict__ x,
                                                const float* __restrict__ dx,
                                                const float* __restrict__ pm,
                                                const float* __restrict__ wq,
                                                const float* __restrict__ wk,
                                                const float* __restrict__ wv,
                                                const float* __restrict__ wo)
{
    __shared__ float shx[32], shd[32];
    const int rg = blockIdx.x;
    const int lane = threadIdx.x & 31, wid = threadIdx.x >> 5;

    if (rg >= M_ + 4 * D_) {                 // ---- pmrm ----
        const int q = rg - M_ - 4 * D_;
        float s = 0.f;
        for (int k = threadIdx.x; k < S_; k += 256) s += pm[(size_t)q * S_ + k];
        #pragma unroll
        for (int o = 16; o; o >>= 1) s += __shfl_xor_sync(0xffffffffu, s, o);
        if (lane == 0) shx[wid] = s;
        __syncthreads();
        if (wid == 0) {
            s = (lane < 8) ? shx[lane] : 0.f;
            #pragma unroll
            for (int o = 4; o; o >>= 1) s += __shfl_xor_sync(0xffffffffu, s, o);
            if (lane == 0) g_pmrm[q] = s / (float)S_;
        }
        return;
    }

    const int c = threadIdx.x * 4;
    if (rg < M_) {
        // ---- x rows: A2 = [xh | xl], plus row_u ----
        const float* src = x + (size_t)rg * D_;
        __half* d0 = g_A2 + (size_t)rg * KX_ + c;
        float4 v = *(const float4*)(src + c);
        __half h0 = __float2half_rn(v.x), h1 = __float2half_rn(v.y);
        __half h2 = __float2half_rn(v.z), h3 = __float2half_rn(v.w);
        __half l0 = __float2half_rn(v.x - __half2float(h0));
        __half l1 = __float2half_rn(v.y - __half2float(h1));
        __half l2 = __float2half_rn(v.z - __half2float(h2));
        __half l3 = __float2half_rn(v.w - __half2float(h3));
        __half2 hA = {h0, h1}, hB = {h2, h3}, lA = {l0, l1}, lB = {l2, l3};
        *(__half2*)(d0)          = hA; *(__half2*)(d0 + 2)      = hB;
        *(__half2*)(d0 + D_)     = lA; *(__half2*)(d0 + D_ + 2) = lB;
        // row_u
        float4 dv = *(const float4*)(dx + (size_t)rg * D_ + c);
        float sx = v.x*v.x + v.y*v.y + v.z*v.z + v.w*v.w;
        float sd = dv.x*dv.x + dv.y*dv.y + dv.z*dv.z + dv.w*dv.w;
        #pragma unroll
        for (int o = 16; o; o >>= 1) {
            sx += __shfl_xor_sync(0xffffffffu, sx, o);
            sd += __shfl_xor_sync(0xffffffffu, sd, o);
        }
        if (lane == 0) { shx[wid] = sx; shd[wid] = sd; }
        __syncthreads();
        if (wid == 0) {
            sx = (lane < 8) ? shx[lane] : 0.f;
            sd = (lane < 8) ? shd[lane] : 0.f;
            #pragma unroll
            for (int o = 4; o; o >>= 1) {
                sx += __shfl_xor_sync(0xffffffffu, sx, o);
                sd += __shfl_xor_sync(0xffffffffu, sd, o);
            }
            if (lane == 0) g_u[rg] = sqrtf(sd) / (sqrtf(sx) + 1e-8f);
        }
    } else {
        // ---- weight rows: W2 = [Wh | Wh] ----
        int idx = rg - M_;
        int j = idx >> 10;
        int row = idx & 1023;
        const float* w = (j == 0) ? wq : (j == 1) ? wk : (j == 2) ? wv : wo;
        const float* src = w + (size_t)row * D_;
        __half* d0 = g_W2 + ((size_t)j * D_ + row) * KX_ + c;
        float4 v = *(const float4*)(src + c);
        __half h0 = __float2half_rn(v.x), h1 = __float2half_rn(v.y);
        __half h2 = __float2half_rn(v.z), h3 = __float2half_rn(v.w);
        __half2 hA = {h0, h1}, hB = {h2, h3};
        *(__half2*)(d0)          = hA; *(__half2*)(d0 + 2)      = hB;
        *(__half2*)(d0 + D_)     = hA; *(__half2*)(d0 + D_ + 2) = hB;
    }
}

__global__ void __launch_bounds__(256) lam_kernel()
{
    const int b = blockIdx.x;
    float s = 0.f;
    for (int i = threadIdx.x; i < S_; i += 256) s += g_u[b * S_ + i];
    __shared__ float sh[32];
    int lane = threadIdx.x & 31, wid = threadIdx.x >> 5;
    #pragma unroll
    for (int o = 16; o; o >>= 1) s += __shfl_xor_sync(0xffffffffu, s, o);
    if (lane == 0) sh[wid] = s;
    __syncthreads();
    if (wid == 0) {
        s = (lane < 8) ? sh[lane] : 0.f;
        #pragma unroll
        for (int o = 4; o; o >>= 1) s += __shfl_xor_sync(0xffffffffu, s, o);
        if (lane == 0) g_lam[b] = 10.0f * expf(-5.0f * (s / (float)S_));
    }
}

// ---------------- HMMA GEMM (3-stage cp.async pipeline, fp16) -----------------
#define GST 16384
#define GT_TOT (6 * GST)

template<int EPI>
__global__ void __launch_bounds__(256, 2) gemm_mma(const __half* __restrict__ A2,
                                                   const __half* __restrict__ W2,
                                                   const float* __restrict__ b0,
                                                   const float* __restrict__ b1,
                                                   const float* __restrict__ b2,
                                                   float* __restrict__ cout)
{
    extern __shared__ char smem[];
    const uint32_t sA = smem_u32(smem);
    const uint32_t sB = sA + 3 * GST;

    const int t    = threadIdx.x;
    const int lane = t & 31;
    const int w    = t >> 5;
    const int z    = blockIdx.x >> 3;
    const float* bias = (z == 0) ? b0 : (z == 1) ? b1 : b2;

    const int wm = (w & 3) * 32;
    const int wn = (w >> 2) * 64;

    const int ch   = t & 7;
    const int rb   = t >> 3;
    const int swch = ch ^ (rb & 7);
    const __half* gAp[4];
    const __half* gBp[4];
    uint32_t smA[4], smB[4];
    #pragma unroll
    for (int p = 0; p < 4; p++) {
        int row = rb + p * 32;
        gAp[p] = A2 + ((size_t)blockIdx.y * 128 + row) * KX_ + ch * 8;
        gBp[p] = W2 + ((size_t)blockIdx.x * 128 + row) * KX_ + ch * 8;
        smA[p] = sA + row * 128 + swch * 16;
        smB[p] = sB + row * 128 + swch * 16;
    }

    auto load_chunk = [&](int kc, int st) {
        const size_t goff = (size_t)kc * 64;
        #pragma unroll
        for (int p = 0; p < 4; p++) {
            CP_ASYNC16(smA[p] + st * GST, gAp[p] + goff);
            CP_ASYNC16(smB[p] + st * GST, gBp[p] + goff);
        }
    };

    float acc[2][8][4];
    #pragma unroll
    for (int i = 0; i < 2; i++)
        #pragma unroll
        for (int j = 0; j < 8; j++)
            #pragma unroll
            for (int k = 0; k < 4; k++) acc[i][j][k] = 0.f;

    load_chunk(0, 0); CP_COMMIT();
    load_chunk(1, 1); CP_COMMIT();

    const int lrow = lane & 15;
    const int lhalf = lane >> 4;

    int st = 0;
    for (int kc = 0; kc < NC_; kc++) {
        CP_WAIT1();
        __syncthreads();
        if (kc + 2 < NC_) {
            int ns = st + 2; if (ns >= 3) ns -= 3;
            load_chunk(kc + 2, ns);
        }
        CP_COMMIT();

        const uint32_t bA = sA + st * GST;
        const uint32_t bB = sB + st * GST;

        #pragma unroll
        for (int ks = 0; ks < 4; ks++) {
            uint32_t af[2][4];
            #pragma unroll
            for (int mi = 0; mi < 2; mi++) {
                int row = wm + mi * 16 + lrow;
                int chk = (ks * 2 + lhalf) ^ (row & 7);
                ldsm4(af[mi][0], af[mi][1], af[mi][2], af[mi][3],
                      bA + row * 128 + chk * 16);
            }
            #pragma unroll
            for (int nj = 0; nj < 4; nj++) {
                uint32_t r0, r1, r2, r3;
                int row = wn + nj * 16 + lrow;
                int chk = (ks * 2 + lhalf) ^ (row & 7);
                ldsm4(r0, r1, r2, r3, bB + row * 128 + chk * 16);
                #pragma unroll
                for (int mi = 0; mi < 2; mi++) {
                    mma_f16(acc[mi][nj * 2 + 0], af[mi], r0, r2);
                    mma_f16(acc[mi][nj * 2 + 1], af[mi], r1, r3);
                }
            }
        }
        if (++st == 3) st = 0;
    }

    const int tr = lane >> 2;
    const int tc = (lane & 3) * 2;
    const int gy = blockIdx.y * 128;
    const int gxz = (blockIdx.x & 7) * 128;

    if (EPI == 0) {
        #pragma unroll
        for (int mi = 0; mi < 2; mi++)
            #pragma unroll
            for (int nj = 0; nj < 8; nj++) {
                int col = gxz + wn + nj * 8 + tc;
                float2 bv = *(const float2*)(bias + col);
                int row0 = gy + wm + mi * 16 + tr;
                float2 o0 = { acc[mi][nj][0] + bv.x, acc[mi][nj][1] + bv.y };
                float2 o1 = { acc[mi][nj][2] + bv.x, acc[mi][nj][3] + bv.y };
                *(float2*)(cout + (size_t)row0 * D_ + col)       = o0;
                *(float2*)(cout + (size_t)(row0 + 8) * D_ + col) = o1;
            }
    } else {
        #pragma unroll
        for (int mi = 0; mi < 2; mi++)
            #pragma unroll
            for (int nj = 0; nj < 8; nj++) {
                int col = gxz + wn + nj * 8 + tc;
                float2 bv = *(const float2*)(bias + col);
                #pragma unroll
                for (int rr = 0; rr < 2; rr++) {
                    int row = gy + wm + mi * 16 + tr + rr * 8;
                    float v0 = acc[mi][nj][rr * 2 + 0] + bv.x;
                    float v1 = acc[mi][nj][rr * 2 + 1] + bv.y;
                    __half h0 = __float2half_rn(v0);
                    __half h1 = __float2half_rn(v1);
                    if (z == 0) {               // Q: single limb
                        __half2 hp = {h0, h1};
                        *(__half2*)(g_Qh + (size_t)row * D_ + col) = hp;
                    } else if (z == 1) {        // K: 2 limbs
                        __half e0 = __float2half_rn(v0 - __half2float(h0));
                        __half e1 = __float2half_rn(v1 - __half2float(h1));
                        __half2 hp = {h0, h1}, lp = {e0, e1};
                        *(__half2*)(g_Kh + (size_t)row * D_ + col) = hp;
                        *(__half2*)(g_Kl + (size_t)row * D_ + col) = lp;
                    } else {                    // V: 2 limbs, transposed
                        __half e0 = __float2half_rn(v0 - __half2float(h0));
                        __half e1 = __float2half_rn(v1 - __half2float(h1));
                        int bb = row >> 11, s = row & 2047;
                        int hh = col >> 6, dl = col & 63;
                        size_t base = ((size_t)(bb * H_ + hh) * 64 + dl) * S_ + s;
                        g_Vth[base] = h0; g_Vtl[base] = e0;
                        g_Vth[base + S_] = h1; g_Vtl[base + S_] = e1;
                    }
                }
            }
    }
}

// ---------------- HMMA flash attention (fp16; QK 2-prod, PV 2-prod) -----------
#define AS_Q  0
#define AS_KV 16384      // + buf*32768: [Kh 8K][Kl 8K][Vh 8K][Vl 8K]
#define AS_TOT 81920

__global__ void __launch_bounds__(256, 2) attn_mma(const float* __restrict__ pm,
                                                   __half* __restrict__ A2out)
{
    extern __shared__ char smem[];
    const uint32_t base = smem_u32(smem);
    const int b = blockIdx.z, h = blockIdx.y, qt = blockIdx.x;
    const int t = threadIdx.x;
    const int lane = t & 31;
    const int w = t >> 5;
    const float lamv = g_lam[b];
    const bool doclip = (lamv > 1.0f);

    // Q tile (hi limb only): 128 rows x 128B
    #pragma unroll
    for (int i = 0; i < 4; i++) {
        int cid = t + i * 256;             // 0..1023
        int r = cid >> 3, ch = cid & 7;
        size_t go = ((size_t)(b * S_ + qt * 128 + r)) * D_ + h * HD_ + ch * 8;
        uint32_t so = base + AS_Q + r * 128 + ((ch ^ (r & 7)) * 16);
        CP_ASYNC16(so, g_Qh + go);
    }
    auto load_kv = [&](int kt, int buf) {
        uint32_t sb = base + AS_KV + buf * 32768;
        #pragma unroll
        for (int i = 0; i < 2; i++) {
            int cid = t + i * 256;
            int r = cid >> 3, ch = cid & 7;
            uint32_t sw = (ch ^ (r & 7)) * 16;
            size_t gk = ((size_t)(b * S_ + kt * 64 + r)) * D_ + h * HD_ + ch * 8;
            size_t gv = ((size_t)((b * H_ + h) * 64 + r)) * S_ + kt * 64 + ch * 8;
            uint32_t so = sb + r * 128 + sw;
            CP_ASYNC16(so,         g_Kh + gk);
            CP_ASYNC16(so + 8192,  g_Kl + gk);
            CP_ASYNC16(so + 16384, g_Vth + gv);
            CP_ASYNC16(so + 24576, g_Vtl + gv);
        }
    };
    load_kv(0, 0);
    CP_COMMIT();
    load_kv(1, 1);
    CP_COMMIT();

    const int lrow = lane & 15;
    const int lhalf = lane >> 4;
    const int tr = lane >> 2;
    const int tc = (lane & 3) * 2;
    const int qrow0 = qt * 128 + w * 16 + tr;
    const float thr0 = lamv * g_pmrm[qrow0];
    const float thr1 = lamv * g_pmrm[qrow0 + 8];

    float m0 = -1e30f, m1 = -1e30f, l0 = 0.f, l1 = 0.f;
    float oacc[8][4];
    #pragma unroll
    for (int j = 0; j < 8; j++)
        #pragma unroll
        for (int k = 0; k < 4; k++) oacc[j][k] = 0.f;

    const float* pmr0 = pm + (size_t)qrow0 * S_ + tc;
    const float* pmr1 = pmr0 + (size_t)8 * S_;
    const int arow = w * 16 + lrow;

    for (int kt = 0; kt < NIT; kt++) {
        CP_WAIT1();
        __syncthreads();
        const int buf = kt & 1;
        const uint32_t bK = base + AS_KV + buf * 32768;
        const uint32_t bV = bK + 16384;

        // prefetch pm for this tile
        float2 pmv0[8], pmv1[8];
        #pragma unroll
        for (int nt = 0; nt < 8; nt++) {
            pmv0[nt] = *(const float2*)(pmr0 + kt * 64 + nt * 8);
            pmv1[nt] = *(const float2*)(pmr1 + kt * 64 + nt * 8);
        }

        float acc[8][4];
        #pragma unroll
        for (int j = 0; j < 8; j++)
            #pragma unroll
            for (int k = 0; k < 4; k++) acc[j][k] = 0.f;

        // ---- S = Qh*Kh + Qh*Kl ----
        #pragma unroll
        for (int ks = 0; ks < 4; ks++) {
            uint32_t ah[4];
            int achk = ((ks * 2 + lhalf) ^ (arow & 7)) * 16;
            ldsm4(ah[0], ah[1], ah[2], ah[3], base + AS_Q + arow * 128 + achk);
            #pragma unroll
            for (int nj = 0; nj < 4; nj++) {
                int brow = nj * 16 + lrow;
                int bchk = ((ks * 2 + lhalf) ^ (brow & 7)) * 16;
                uint32_t kh0, kh1, kh2, kh3, kl0, kl1, kl2, kl3;
                ldsm4(kh0, kh1, kh2, kh3, bK + brow * 128 + bchk);
                ldsm4(kl0, kl1, kl2, kl3, bK + 8192 + brow * 128 + bchk);
                mma_f16(acc[nj * 2],     ah, kh0, kh2);
                mma_f16(acc[nj * 2 + 1], ah, kh1, kh3);
                mma_f16(acc[nj * 2],     ah, kl0, kl2);
                mma_f16(acc[nj * 2 + 1], ah, kl1, kl3);
            }
        }

        // ---- bias + clip + online softmax ----
        float mx0 = -1e30f, mx1 = -1e30f;
        #pragma unroll
        for (int nt = 0; nt < 8; nt++) {
            float L;
            L = fmaf(lamv, pmv0[nt].x, acc[nt][0] * 0.125f);
            if (doclip && L < thr0) L = -1e30f;
            acc[nt][0] = L; mx0 = fmaxf(mx0, L);
            L = fmaf(lamv, pmv0[nt].y, acc[nt][1] * 0.125f);
            if (doclip && L < thr0) L = -1e30f;
            acc[nt][1] = L; mx0 = fmaxf(mx0, L);
            L = fmaf(lamv, pmv1[nt].x, acc[nt][2] * 0.125f);
            if (doclip && L < thr1) L = -1e30f;
            acc[nt][2] = L; mx1 = fmaxf(mx1, L);
            L = fmaf(lamv, pmv1[nt].y, acc[nt][3] * 0.125f);
            if (doclip && L < thr1) L = -1e30f;
            acc[nt][3] = L; mx1 = fmaxf(mx1, L);
        }
        mx0 = fmaxf(mx0, __shfl_xor_sync(0xffffffffu, mx0, 1));
        mx0 = fmaxf(mx0, __shfl_xor_sync(0xffffffffu, mx0, 2));
        mx1 = fmaxf(mx1, __shfl_xor_sync(0xffffffffu, mx1, 1));
        mx1 = fmaxf(mx1, __shfl_xor_sync(0xffffffffu, mx1, 2));
        float mn0 = fmaxf(m0, mx0), mn1 = fmaxf(m1, mx1);
        float sc0 = __expf(m0 - mn0), sc1 = __expf(m1 - mn1);
        float s0 = 0.f, s1 = 0.f;
        #pragma unroll
        for (int nt = 0; nt < 8; nt++) {
            float p;
            p = __expf(acc[nt][0] - mn0); acc[nt][0] = p; s0 += p;
            p = __expf(acc[nt][1] - mn0); acc[nt][1] = p; s0 += p;
            p = __expf(acc[nt][2] - mn1); acc[nt][2] = p; s1 += p;
            p = __expf(acc[nt][3] - mn1); acc[nt][3] = p; s1 += p;
        }
        s0 += __shfl_xor_sync(0xffffffffu, s0, 1);
        s0 += __shfl_xor_sync(0xffffffffu, s0, 2);
        s1 += __shfl_xor_sync(0xffffffffu, s1, 1);
        s1 += __shfl_xor_sync(0xffffffffu, s1, 2);
        l0 = fmaf(l0, sc0, s0); m0 = mn0;
        l1 = fmaf(l1, sc1, s1); m1 = mn1;
        #pragma unroll
        for (int nt = 0; nt < 8; nt++) {
            oacc[nt][0] *= sc0; oacc[nt][1] *= sc0;
            oacc[nt][2] *= sc1; oacc[nt][3] *= sc1;
        }

        // ---- O += Ph*Vh + Ph*Vl ----
        #pragma unroll
        for (int ks = 0; ks < 4; ks++) {
            const int na = 2 * ks, nb2 = 2 * ks + 1;
            uint32_t aph[4];
            aph[0] = pk_f16(acc[na][0],  acc[na][1]);
            aph[1] = pk_f16(acc[na][2],  acc[na][3]);
            aph[2] = pk_f16(acc[nb2][0], acc[nb2][1]);
            aph[3] = pk_f16(acc[nb2][2], acc[nb2][3]);
            #pragma unroll
            for (int nj = 0; nj < 4; nj++) {
                int brow = nj * 16 + lrow;
                int bchk = ((ks * 2 + lhalf) ^ (brow & 7)) * 16;
                uint32_t vh0, vh1, vh2, vh3, vl0, vl1, vl2, vl3;
                ldsm4(vh0, vh1, vh2, vh3, bV + brow * 128 + bchk);
                ldsm4(vl0, vl1, vl2, vl3, bV + 8192 + brow * 128 + bchk);
                mma_f16(oacc[nj * 2],     aph, vh0, vh2);
                mma_f16(oacc[nj * 2 + 1], aph, vh1, vh3);
                mma_f16(oacc[nj * 2],     aph, vl0, vl2);
                mma_f16(oacc[nj * 2 + 1], aph, vl1, vl3);
            }
        }

        __syncthreads();
        if (kt + 2 < NIT) load_kv(kt + 2, buf);
        CP_COMMIT();
    }

    // ---- epilogue: normalize and write [oh | ol] into A2 ----
    const float inv0 = 1.0f / l0, inv1 = 1.0f / l1;
    const size_t row0 = (size_t)(b * S_) + qt * 128 + w * 16 + tr;
    #pragma unroll
    for (int nt = 0; nt < 8; nt++) {
        int col = h * HD_ + nt * 8 + tc;
        #pragma unroll
        for (int rr = 0; rr < 2; rr++) {
            float v0 = oacc[nt][rr * 2 + 0] * (rr ? inv1 : inv0);
            float v1 = oacc[nt][rr * 2 + 1] * (rr ? inv1 : inv0);
            __half h0 = __float2half_rn(v0);
            __half h1 = __float2half_rn(v1);
            __half e0 = __float2half_rn(v0 - __half2float(h0));
            __half e1 = __float2half_rn(v1 - __half2float(h1));
            __half2 hp = {h0, h1}, lp = {e0, e1};
            __half* dst = A2out + (row0 + rr * 8) * KX_ + col;
            *(__half2*)(dst)      = hp;
            *(__half2*)(dst + D_) = lp;
        }
    }
}

// ---------------- launch ------------------------------------------------------
extern "C" void kernel_launch(void* const* d_in, const int* in_sizes, int n_in,
                              void* d_out, int out_size)
{
    const float* x  = (const float*)d_in[0];
    const float* pm = (const float*)d_in[1];
    const float* dx = (const float*)d_in[2];
    const float* wq = (const float*)d_in[3];
    const float* bq = (const float*)d_in[4];
    const float* wk = (const float*)d_in[5];
    const float* bk = (const float*)d_in[6];
    const float* wv = (const float*)d_in[7];
    const float* bv = (const float*)d_in[8];
    const float* wo = (const float*)d_in[9];
    const float* bo = (const float*)d_in[10];
    float* out = (float*)d_out;

    __half *gA2, *gW2;
    cudaGetSymbolAddress((void**)&gA2, g_A2);
    cudaGetSymbolAddress((void**)&gW2, g_W2);

    cudaFuncSetAttribute(gemm_mma<0>, cudaFuncAttributeMaxDynamicSharedMemorySize, GT_TOT);
    cudaFuncSetAttribute(gemm_mma<1>, cudaFuncAttributeMaxDynamicSharedMemorySize, GT_TOT);
    cudaFuncSetAttribute(attn_mma, cudaFuncAttributeMaxDynamicSharedMemorySize, AS_TOT);

    // fused prologue: splits + row_u + pmrm, then lam
    prologue<<<M_ + 4 * D_ + S_, 256>>>(x, dx, pm, wq, wk, wv, wo);
    lam_kernel<<<B_, 256>>>();

    // fused QKV projection: single GEMM, N = 3072 (q|k|v stacked), K = 2048
    dim3 gqkv(3 * D_ / 128, M_ / 128);
    gemm_mma<1><<<gqkv, 256, GT_TOT>>>(gA2, gW2, bq, bk, bv, nullptr);

    // HMMA flash attention (fp16) -> writes A2 [oh|ol] directly
    dim3 ag(S_ / 128, H_, B_);
    attn_mma<<<ag, 256, AS_TOT>>>(pm, gA2);

    // output projection
    dim3 go(D_ / 128, M_ / 128);
    gemm_mma<0><<<go, 256, GT_TOT>>>(gA2, gW2 + 3 * (size_t)D_ * KX_, bo, bo, bo, out);
}